// round 1
// baseline (speedup 1.0000x reference)
#include <cuda_runtime.h>
#include <math_constants.h>

#define BB   2
#define LL   2048
#define DD   1024
#define HH   16
#define DHH  64

// Scratch (allocation-free: device globals)
__device__ float g_qkv[(size_t)BB * LL * 3 * DD];   // [B*L, 3D]
__device__ float g_att[(size_t)BB * LL * DD];       // [B*L, D] (b,l,h,dh)

// ---------------------------------------------------------------------------
// SGEMM: C[M,N] = A[M,K] @ B[K,N] + bias[N]
// 128x128 block tile, BK=8, 8x8 per-thread microtile (split 4+4), 256 threads
// ---------------------------------------------------------------------------
__global__ __launch_bounds__(256) void sgemm_bias_kernel(
    const float* __restrict__ A, const float* __restrict__ Bm,
    const float* __restrict__ bias, float* __restrict__ C,
    int M, int N, int K)
{
    constexpr int BM = 128, BN = 128, BK = 8;
    __shared__ float As[BK][BM];
    __shared__ float Bs[BK][BN];

    const int tid = threadIdx.x;
    const int bm  = blockIdx.y * BM;
    const int bn  = blockIdx.x * BN;

    const int arow = tid >> 1;          // 0..127
    const int acol = (tid & 1) << 2;    // 0 or 4
    const int brow = tid >> 5;          // 0..7
    const int bcol = (tid & 31) << 2;   // 0..124

    const int ty = tid >> 4;            // 0..15
    const int tx = tid & 15;            // 0..15

    float acc[8][8];
    #pragma unroll
    for (int i = 0; i < 8; i++)
        #pragma unroll
        for (int j = 0; j < 8; j++) acc[i][j] = 0.0f;

    for (int k0 = 0; k0 < K; k0 += BK) {
        float4 a4 = *(const float4*)(A + (size_t)(bm + arow) * K + k0 + acol);
        As[acol + 0][arow] = a4.x;
        As[acol + 1][arow] = a4.y;
        As[acol + 2][arow] = a4.z;
        As[acol + 3][arow] = a4.w;
        *(float4*)&Bs[brow][bcol] =
            *(const float4*)(Bm + (size_t)(k0 + brow) * N + bn + bcol);
        __syncthreads();

        #pragma unroll
        for (int kk = 0; kk < BK; kk++) {
            float4 a0 = *(const float4*)&As[kk][ty * 4];
            float4 a1 = *(const float4*)&As[kk][64 + ty * 4];
            float4 b0 = *(const float4*)&Bs[kk][tx * 4];
            float4 b1 = *(const float4*)&Bs[kk][64 + tx * 4];
            float ar[8] = {a0.x, a0.y, a0.z, a0.w, a1.x, a1.y, a1.z, a1.w};
            float br[8] = {b0.x, b0.y, b0.z, b0.w, b1.x, b1.y, b1.z, b1.w};
            #pragma unroll
            for (int i = 0; i < 8; i++)
                #pragma unroll
                for (int j = 0; j < 8; j++)
                    acc[i][j] += ar[i] * br[j];
        }
        __syncthreads();
    }

    #pragma unroll
    for (int i = 0; i < 8; i++) {
        int row = bm + ((i < 4) ? (ty * 4 + i) : (64 + ty * 4 + (i - 4)));
        #pragma unroll
        for (int jh = 0; jh < 2; jh++) {
            int col = bn + jh * 64 + tx * 4;
            float4 o;
            o.x = acc[i][jh * 4 + 0] + bias[col + 0];
            o.y = acc[i][jh * 4 + 1] + bias[col + 1];
            o.z = acc[i][jh * 4 + 2] + bias[col + 2];
            o.w = acc[i][jh * 4 + 3] + bias[col + 3];
            *(float4*)(C + (size_t)row * N + col) = o;
        }
    }
}

// ---------------------------------------------------------------------------
// Fused causal ALiBi attention, fp32, flash-style online softmax.
// Grid: (L/64 q-tiles, B*H). Block: 256 threads.
// Per block: 64 queries; key chunks of 32 (causal skip: only 2*qt+2 chunks).
// Thread (ty,tx): ty=tid/16 -> 4 queries; tx=tid%16 -> 2 keys (scores) / 4 dims (PV).
// ---------------------------------------------------------------------------
__global__ __launch_bounds__(256) void attn_kernel(
    const float* __restrict__ qkv, float* __restrict__ out)
{
    constexpr int QT = 64, KT = 32, DH = DHH;

    __shared__ float Qs[QT][DH + 1];
    __shared__ float Ks[KT][DH + 1];
    __shared__ float Vs[KT][DH + 1];
    __shared__ float Ss[QT][KT + 1];

    const int tid = threadIdx.x;
    const int qt  = blockIdx.x;
    const int bh  = blockIdx.y;
    const int b   = bh >> 4;
    const int h   = bh & 15;

    const float slope = exp2f(-0.5f * (float)(h + 1));
    const float scale = 0.125f;  // 1/sqrt(64)

    const size_t rowstride = 3 * DD;
    const float* base = qkv + (size_t)b * LL * rowstride;
    const int qoff = h * DHH;
    const int koff = DD + h * DHH;
    const int voff = 2 * DD + h * DHH;

    // Load Q tile: 64 x 64
    #pragma unroll
    for (int it = 0; it < 4; it++) {
        int idx = tid + it * 256;            // 0..1023 float4 slots
        int r = idx >> 4;
        int c = (idx & 15) << 2;
        float4 v = *(const float4*)(base + (size_t)(qt * QT + r) * rowstride + qoff + c);
        Qs[r][c + 0] = v.x; Qs[r][c + 1] = v.y; Qs[r][c + 2] = v.z; Qs[r][c + 3] = v.w;
    }

    const int ty = tid >> 4;
    const int tx = tid & 15;
    const int q0 = ty * 4;
    const int k0l = tx * 2;
    const int d0 = tx * 4;

    float m[4], l[4], O[4][4];
    #pragma unroll
    for (int i = 0; i < 4; i++) {
        m[i] = -1e30f; l[i] = 0.0f;
        #pragma unroll
        for (int j = 0; j < 4; j++) O[i][j] = 0.0f;
    }

    const int nkt = 2 * qt + 2;   // causal: keys 0 .. qt*64+63

    for (int kt = 0; kt < nkt; kt++) {
        __syncthreads();   // protect Ks/Vs (prev reads) and Qs (first iter)

        // Load K,V chunk: 32 x 64 each
        #pragma unroll
        for (int it = 0; it < 2; it++) {
            int idx = tid + it * 256;        // 0..511 float4 slots
            int r = idx >> 4;
            int c = (idx & 15) << 2;
            const float* rp = base + (size_t)(kt * KT + r) * rowstride;
            float4 kv = *(const float4*)(rp + koff + c);
            Ks[r][c + 0] = kv.x; Ks[r][c + 1] = kv.y; Ks[r][c + 2] = kv.z; Ks[r][c + 3] = kv.w;
            float4 vv = *(const float4*)(rp + voff + c);
            Vs[r][c + 0] = vv.x; Vs[r][c + 1] = vv.y; Vs[r][c + 2] = vv.z; Vs[r][c + 3] = vv.w;
        }
        __syncthreads();

        // Scores: 4 queries x 2 keys per thread
        float s[4][2];
        #pragma unroll
        for (int i = 0; i < 4; i++) { s[i][0] = 0.0f; s[i][1] = 0.0f; }

        #pragma unroll
        for (int d = 0; d < DH; d++) {
            float kv0 = Ks[k0l + 0][d];
            float kv1 = Ks[k0l + 1][d];
            #pragma unroll
            for (int i = 0; i < 4; i++) {
                float qv = Qs[q0 + i][d];
                s[i][0] += qv * kv0;
                s[i][1] += qv * kv1;
            }
        }

        // Scale + ALiBi + causal mask
        const int qg0 = qt * QT + q0;
        const int kg0 = kt * KT + k0l;
        #pragma unroll
        for (int i = 0; i < 4; i++) {
            #pragma unroll
            for (int j = 0; j < 2; j++) {
                int qg = qg0 + i, kg = kg0 + j;
                if (kg <= qg)
                    s[i][j] = s[i][j] * scale + slope * (float)(kg - qg);
                else
                    s[i][j] = -1e30f;
            }
        }

        // Online softmax update (reduce across the 16-lane tx group)
        #pragma unroll
        for (int i = 0; i < 4; i++) {
            float mv = fmaxf(s[i][0], s[i][1]);
            #pragma unroll
            for (int o = 1; o < 16; o <<= 1)
                mv = fmaxf(mv, __shfl_xor_sync(0xffffffffu, mv, o));
            float mnew = fmaxf(m[i], mv);

            s[i][0] = __expf(s[i][0] - mnew);
            s[i][1] = __expf(s[i][1] - mnew);
            float rs = s[i][0] + s[i][1];
            #pragma unroll
            for (int o = 1; o < 16; o <<= 1)
                rs += __shfl_xor_sync(0xffffffffu, rs, o);

            float corr = __expf(m[i] - mnew);
            l[i] = l[i] * corr + rs;
            m[i] = mnew;
            #pragma unroll
            for (int j = 0; j < 4; j++) O[i][j] *= corr;
        }

        // Store P
        #pragma unroll
        for (int i = 0; i < 4; i++) {
            Ss[q0 + i][k0l + 0] = s[i][0];
            Ss[q0 + i][k0l + 1] = s[i][1];
        }
        __syncthreads();

        // O += P @ V  (thread: 4 queries x 4 dims)
        #pragma unroll
        for (int k = 0; k < KT; k++) {
            float vv0 = Vs[k][d0 + 0];
            float vv1 = Vs[k][d0 + 1];
            float vv2 = Vs[k][d0 + 2];
            float vv3 = Vs[k][d0 + 3];
            #pragma unroll
            for (int i = 0; i < 4; i++) {
                float p = Ss[q0 + i][k];
                O[i][0] += p * vv0;
                O[i][1] += p * vv1;
                O[i][2] += p * vv2;
                O[i][3] += p * vv3;
            }
        }
    }

    // Write normalized output: out[b, qg, h*64 + d]
    #pragma unroll
    for (int i = 0; i < 4; i++) {
        int qg = qt * QT + q0 + i;
        float inv = 1.0f / l[i];
        float4 o4;
        o4.x = O[i][0] * inv; o4.y = O[i][1] * inv;
        o4.z = O[i][2] * inv; o4.w = O[i][3] * inv;
        *(float4*)(out + ((size_t)b * LL + qg) * DD + h * DHH + d0) = o4;
    }
}

// ---------------------------------------------------------------------------
extern "C" void kernel_launch(void* const* d_in, const int* in_sizes, int n_in,
                              void* d_out, int out_size)
{
    const float* x     = (const float*)d_in[0];   // [B,L,D]
    const float* w_in  = (const float*)d_in[1];   // [D,3D]
    const float* b_in  = (const float*)d_in[2];   // [3D]
    const float* w_out = (const float*)d_in[3];   // [D,D]
    const float* b_out = (const float*)d_in[4];   // [D]
    float* out = (float*)d_out;                   // [B,L,D]

    float* qkv = nullptr;
    float* att = nullptr;
    cudaGetSymbolAddress((void**)&qkv, g_qkv);
    cudaGetSymbolAddress((void**)&att, g_att);

    const int M = BB * LL;   // 8192

    // 1) QKV projection: [8192,1024] @ [1024,3072] + b_in
    {
        dim3 grid(3 * DD / 128, M / 128);
        sgemm_bias_kernel<<<grid, 256>>>(x, w_in, b_in, qkv, M, 3 * DD, DD);
    }

    // 2) Fused causal ALiBi attention
    {
        dim3 grid(LL / 64, BB * HH);
        attn_kernel<<<grid, 256>>>(qkv, att);
    }

    // 3) Output projection: [8192,1024] @ [1024,1024] + b_out
    {
        dim3 grid(DD / 128, M / 128);
        sgemm_bias_kernel<<<grid, 256>>>(att, w_out, b_out, out, M, DD, DD);
    }
}

// round 3
// speedup vs baseline: 1.2087x; 1.2087x over previous
#include <cuda_runtime.h>
#include <cstdint>

#define BB   2
#define LL   2048
#define DD   1024
#define HH   16
#define DHH  64

// Scratch (allocation-free: device globals)
__device__ float g_qkv[(size_t)BB * LL * 3 * DD];   // [B*L, 3D]
__device__ float g_att[(size_t)BB * LL * DD];       // [B*L, D] (b,l,h,dh)
__device__ float g_wtin[(size_t)3 * DD * DD];       // w_in^T  [3D, D]
__device__ float g_wtout[(size_t)DD * DD];          // w_out^T [D, D]

// ---------------------------------------------------------------------------
// helpers
// ---------------------------------------------------------------------------
__device__ __forceinline__ uint32_t f2tf32(float x) {
    uint32_t r;
    asm("cvt.rna.tf32.f32 %0, %1;" : "=r"(r) : "f"(x));
    return r;
}

__device__ __forceinline__ void mma_tf32(float* d, const uint32_t* a,
                                         const uint32_t* b) {
    asm volatile(
        "mma.sync.aligned.m16n8k8.row.col.f32.tf32.tf32.f32 "
        "{%0,%1,%2,%3}, {%4,%5,%6,%7}, {%8,%9}, {%0,%1,%2,%3};"
        : "+f"(d[0]), "+f"(d[1]), "+f"(d[2]), "+f"(d[3])
        : "r"(a[0]), "r"(a[1]), "r"(a[2]), "r"(a[3]),
          "r"(b[0]), "r"(b[1]));
}

// ---------------------------------------------------------------------------
// Transpose: out[c][r] = in[r][c].  in: [R, C] row-major.
// ---------------------------------------------------------------------------
__global__ __launch_bounds__(256) void transpose_kernel(
    const float* __restrict__ in, float* __restrict__ out, int R, int C)
{
    __shared__ float tile[32][33];
    int bx = blockIdx.x * 32, by = blockIdx.y * 32;
    int x = bx + threadIdx.x;
    #pragma unroll
    for (int i = 0; i < 32; i += 8) {
        int y = by + threadIdx.y + i;
        tile[threadIdx.y + i][threadIdx.x] = in[(size_t)y * C + x];
    }
    __syncthreads();
    int ox = by + threadIdx.x;
    #pragma unroll
    for (int i = 0; i < 32; i += 8) {
        int oy = bx + threadIdx.y + i;
        out[(size_t)oy * R + ox] = tile[threadIdx.x][threadIdx.y + i];
    }
}

// ---------------------------------------------------------------------------
// tf32 mma.sync GEMM: C[M,N] = A[M,K] @ Bt[N,K]^T + bias[N]
// CTA 128x128, BK=32, 8 warps (warp tile 64M x 32N, 4x4 m16n8k8 frags).
// Double-buffered smem, register-staged global loads. 256 threads.
// ---------------------------------------------------------------------------
#define PADK 36   // 32 + 4 pad (floats per row)

__global__ __launch_bounds__(256) void gemm_tf32_kernel(
    const float* __restrict__ A, const float* __restrict__ Bt,
    const float* __restrict__ bias, float* __restrict__ C,
    int M, int N, int K)
{
    extern __shared__ uint32_t smem[];
    // layout (uint32 units): As[2][128][PADK], Bs[2][128][PADK]
    uint32_t* Abuf[2] = { smem,               smem + 128 * PADK };
    uint32_t* Bbuf[2] = { smem + 2 * 128 * PADK, smem + 3 * 128 * PADK };

    const int tid = threadIdx.x;
    const int wid = tid >> 5;
    const int lid = tid & 31;
    const int gid = lid >> 2;       // 0..7
    const int tig = lid & 3;        // 0..3

    const int bm = blockIdx.y * 128;
    const int bn = blockIdx.x * 128;

    const int warp_m = wid & 1;     // 0..1 -> 64 rows each
    const int warp_n = wid >> 1;    // 0..3 -> 32 cols each
    const int mbase = warp_m * 64;
    const int nbase = warp_n * 32;

    // global load geometry: per tile 128 rows x 8 float4; thread covers
    // rows (tid>>3)+32*i, 16B-chunk (tid&7)
    const int grow = tid >> 3;
    const int gc4  = tid & 7;

    float acc[4][4][4];
    #pragma unroll
    for (int i = 0; i < 4; i++)
        #pragma unroll
        for (int j = 0; j < 4; j++)
            #pragma unroll
            for (int e = 0; e < 4; e++) acc[i][j][e] = 0.0f;

    const int NC = K >> 5;   // K/32

    float4 pa[4], pb[4];

    // prologue: load chunk 0
    #pragma unroll
    for (int i = 0; i < 4; i++) {
        int r = grow + 32 * i;
        pa[i] = *(const float4*)(A  + (size_t)(bm + r) * K + gc4 * 4);
        pb[i] = *(const float4*)(Bt + (size_t)(bn + r) * K + gc4 * 4);
    }
    {
        uint32_t* As = Abuf[0];
        uint32_t* Bs = Bbuf[0];
        #pragma unroll
        for (int i = 0; i < 4; i++) {
            int r = grow + 32 * i;
            uint32_t* ap = As + r * PADK + gc4 * 4;
            ap[0] = f2tf32(pa[i].x); ap[1] = f2tf32(pa[i].y);
            ap[2] = f2tf32(pa[i].z); ap[3] = f2tf32(pa[i].w);
            uint32_t* bp = Bs + r * PADK + gc4 * 4;
            bp[0] = f2tf32(pb[i].x); bp[1] = f2tf32(pb[i].y);
            bp[2] = f2tf32(pb[i].z); bp[3] = f2tf32(pb[i].w);
        }
    }
    __syncthreads();

    for (int c = 0; c < NC; c++) {
        // stage next chunk's global loads
        if (c + 1 < NC) {
            const float* Ab = A  + (size_t)bm * K + (c + 1) * 32;
            const float* Bb = Bt + (size_t)bn * K + (c + 1) * 32;
            #pragma unroll
            for (int i = 0; i < 4; i++) {
                int r = grow + 32 * i;
                pa[i] = *(const float4*)(Ab + (size_t)r * K + gc4 * 4);
                pb[i] = *(const float4*)(Bb + (size_t)r * K + gc4 * 4);
            }
        }

        // compute on buffer c&1
        {
            const uint32_t* As = Abuf[c & 1];
            const uint32_t* Bs = Bbuf[c & 1];
            #pragma unroll
            for (int ks = 0; ks < 4; ks++) {
                const int k0 = ks * 8;
                uint32_t af[4][4], bf[4][2];
                #pragma unroll
                for (int i = 0; i < 4; i++) {
                    const uint32_t* r0 = As + (mbase + i * 16 + gid) * PADK + k0 + tig;
                    const uint32_t* r1 = r0 + 8 * PADK;
                    af[i][0] = r0[0]; af[i][1] = r1[0];
                    af[i][2] = r0[4]; af[i][3] = r1[4];
                }
                #pragma unroll
                for (int j = 0; j < 4; j++) {
                    const uint32_t* r0 = Bs + (nbase + j * 8 + gid) * PADK + k0 + tig;
                    bf[j][0] = r0[0]; bf[j][1] = r0[4];
                }
                #pragma unroll
                for (int i = 0; i < 4; i++)
                    #pragma unroll
                    for (int j = 0; j < 4; j++)
                        mma_tf32(acc[i][j], af[i], bf[j]);
            }
        }

        // store staged regs into the other buffer
        if (c + 1 < NC) {
            uint32_t* As = Abuf[(c + 1) & 1];
            uint32_t* Bs = Bbuf[(c + 1) & 1];
            #pragma unroll
            for (int i = 0; i < 4; i++) {
                int r = grow + 32 * i;
                uint32_t* ap = As + r * PADK + gc4 * 4;
                ap[0] = f2tf32(pa[i].x); ap[1] = f2tf32(pa[i].y);
                ap[2] = f2tf32(pa[i].z); ap[3] = f2tf32(pa[i].w);
                uint32_t* bp = Bs + r * PADK + gc4 * 4;
                bp[0] = f2tf32(pb[i].x); bp[1] = f2tf32(pb[i].y);
                bp[2] = f2tf32(pb[i].z); bp[3] = f2tf32(pb[i].w);
            }
        }
        __syncthreads();
    }

    // epilogue: write C with bias
    #pragma unroll
    for (int j = 0; j < 4; j++) {
        const int col = bn + nbase + j * 8 + 2 * tig;
        const float bi0 = __ldg(bias + col);
        const float bi1 = __ldg(bias + col + 1);
        #pragma unroll
        for (int i = 0; i < 4; i++) {
            const int row0 = bm + mbase + i * 16 + gid;
            float2 v0 = { acc[i][j][0] + bi0, acc[i][j][1] + bi1 };
            float2 v1 = { acc[i][j][2] + bi0, acc[i][j][3] + bi1 };
            *(float2*)(C + (size_t)row0 * N + col) = v0;
            *(float2*)(C + (size_t)(row0 + 8) * N + col) = v1;
        }
    }
}

// ---------------------------------------------------------------------------
// Fused causal ALiBi attention, fp32, flash-style online softmax.
// Grid: (L/64 q-tiles, B*H). Block: 256 threads.
// ---------------------------------------------------------------------------
__global__ __launch_bounds__(256) void attn_kernel(
    const float* __restrict__ qkv, float* __restrict__ out)
{
    constexpr int QT = 64, KT = 32, DH = DHH;

    __shared__ float Qs[QT][DH + 1];
    __shared__ float Ks[KT][DH + 1];
    __shared__ float Vs[KT][DH + 1];
    __shared__ float Ss[QT][KT + 1];

    const int tid = threadIdx.x;
    const int qt  = blockIdx.x;
    const int bh  = blockIdx.y;
    const int b   = bh >> 4;
    const int h   = bh & 15;

    const float slope = exp2f(-0.5f * (float)(h + 1));
    const float scale = 0.125f;  // 1/sqrt(64)

    const size_t rowstride = 3 * DD;
    const float* base = qkv + (size_t)b * LL * rowstride;
    const int qoff = h * DHH;
    const int koff = DD + h * DHH;
    const int voff = 2 * DD + h * DHH;

    #pragma unroll
    for (int it = 0; it < 4; it++) {
        int idx = tid + it * 256;
        int r = idx >> 4;
        int c = (idx & 15) << 2;
        float4 v = *(const float4*)(base + (size_t)(qt * QT + r) * rowstride + qoff + c);
        Qs[r][c + 0] = v.x; Qs[r][c + 1] = v.y; Qs[r][c + 2] = v.z; Qs[r][c + 3] = v.w;
    }

    const int ty = tid >> 4;
    const int tx = tid & 15;
    const int q0 = ty * 4;
    const int k0l = tx * 2;
    const int d0 = tx * 4;

    float m[4], l[4], O[4][4];
    #pragma unroll
    for (int i = 0; i < 4; i++) {
        m[i] = -1e30f; l[i] = 0.0f;
        #pragma unroll
        for (int j = 0; j < 4; j++) O[i][j] = 0.0f;
    }

    const int nkt = 2 * qt + 2;

    for (int kt = 0; kt < nkt; kt++) {
        __syncthreads();

        #pragma unroll
        for (int it = 0; it < 2; it++) {
            int idx = tid + it * 256;
            int r = idx >> 4;
            int c = (idx & 15) << 2;
            const float* rp = base + (size_t)(kt * KT + r) * rowstride;
            float4 kv = *(const float4*)(rp + koff + c);
            Ks[r][c + 0] = kv.x; Ks[r][c + 1] = kv.y; Ks[r][c + 2] = kv.z; Ks[r][c + 3] = kv.w;
            float4 vv = *(const float4*)(rp + voff + c);
            Vs[r][c + 0] = vv.x; Vs[r][c + 1] = vv.y; Vs[r][c + 2] = vv.z; Vs[r][c + 3] = vv.w;
        }
        __syncthreads();

        float s[4][2];
        #pragma unroll
        for (int i = 0; i < 4; i++) { s[i][0] = 0.0f; s[i][1] = 0.0f; }

        #pragma unroll
        for (int d = 0; d < DH; d++) {
            float kv0 = Ks[k0l + 0][d];
            float kv1 = Ks[k0l + 1][d];
            #pragma unroll
            for (int i = 0; i < 4; i++) {
                float qv = Qs[q0 + i][d];
                s[i][0] += qv * kv0;
                s[i][1] += qv * kv1;
            }
        }

        const int qg0 = qt * QT + q0;
        const int kg0 = kt * KT + k0l;
        #pragma unroll
        for (int i = 0; i < 4; i++) {
            #pragma unroll
            for (int j = 0; j < 2; j++) {
                int qg = qg0 + i, kg = kg0 + j;
                if (kg <= qg)
                    s[i][j] = s[i][j] * scale + slope * (float)(kg - qg);
                else
                    s[i][j] = -1e30f;
            }
        }

        #pragma unroll
        for (int i = 0; i < 4; i++) {
            float mv = fmaxf(s[i][0], s[i][1]);
            #pragma unroll
            for (int o = 1; o < 16; o <<= 1)
                mv = fmaxf(mv, __shfl_xor_sync(0xffffffffu, mv, o));
            float mnew = fmaxf(m[i], mv);

            s[i][0] = __expf(s[i][0] - mnew);
            s[i][1] = __expf(s[i][1] - mnew);
            float rs = s[i][0] + s[i][1];
            #pragma unroll
            for (int o = 1; o < 16; o <<= 1)
                rs += __shfl_xor_sync(0xffffffffu, rs, o);

            float corr = __expf(m[i] - mnew);
            l[i] = l[i] * corr + rs;
            m[i] = mnew;
            #pragma unroll
            for (int j = 0; j < 4; j++) O[i][j] *= corr;
        }

        #pragma unroll
        for (int i = 0; i < 4; i++) {
            Ss[q0 + i][k0l + 0] = s[i][0];
            Ss[q0 + i][k0l + 1] = s[i][1];
        }
        __syncthreads();

        #pragma unroll
        for (int k = 0; k < KT; k++) {
            float vv0 = Vs[k][d0 + 0];
            float vv1 = Vs[k][d0 + 1];
            float vv2 = Vs[k][d0 + 2];
            float vv3 = Vs[k][d0 + 3];
            #pragma unroll
            for (int i = 0; i < 4; i++) {
                float p = Ss[q0 + i][k];
                O[i][0] += p * vv0;
                O[i][1] += p * vv1;
                O[i][2] += p * vv2;
                O[i][3] += p * vv3;
            }
        }
    }

    #pragma unroll
    for (int i = 0; i < 4; i++) {
        int qg = qt * QT + q0 + i;
        float inv = 1.0f / l[i];
        float4 o4;
        o4.x = O[i][0] * inv; o4.y = O[i][1] * inv;
        o4.z = O[i][2] * inv; o4.w = O[i][3] * inv;
        *(float4*)(out + ((size_t)b * LL + qg) * DD + h * DHH + d0) = o4;
    }
}

// ---------------------------------------------------------------------------
extern "C" void kernel_launch(void* const* d_in, const int* in_sizes, int n_in,
                              void* d_out, int out_size)
{
    const float* x     = (const float*)d_in[0];   // [B,L,D]
    const float* w_in  = (const float*)d_in[1];   // [D,3D]
    const float* b_in  = (const float*)d_in[2];   // [3D]
    const float* w_out = (const float*)d_in[3];   // [D,D]
    const float* b_out = (const float*)d_in[4];   // [D]
    float* out = (float*)d_out;                   // [B,L,D]

    float* qkv = nullptr;
    float* att = nullptr;
    float* wtin = nullptr;
    float* wtout = nullptr;
    cudaGetSymbolAddress((void**)&qkv, g_qkv);
    cudaGetSymbolAddress((void**)&att, g_att);
    cudaGetSymbolAddress((void**)&wtin, g_wtin);
    cudaGetSymbolAddress((void**)&wtout, g_wtout);

    const int M = BB * LL;   // 8192
    const int SMEM_BYTES = 4 * 128 * PADK * 4;   // 73728
    static bool attr_set = false;
    if (!attr_set) {
        cudaFuncSetAttribute(gemm_tf32_kernel,
                             cudaFuncAttributeMaxDynamicSharedMemorySize, SMEM_BYTES);
        attr_set = true;
    }

    // 0) Transpose weights to [N, K] (col-major B operand)
    {
        dim3 blk(32, 8);
        transpose_kernel<<<dim3(3 * DD / 32, DD / 32), blk>>>(w_in, wtin, DD, 3 * DD);
        transpose_kernel<<<dim3(DD / 32, DD / 32), blk>>>(w_out, wtout, DD, DD);
    }

    // 1) QKV projection: [8192,1024] @ [1024,3072] + b_in  (tf32 mma.sync)
    {
        dim3 grid(3 * DD / 128, M / 128);
        gemm_tf32_kernel<<<grid, 256, SMEM_BYTES>>>(x, wtin, b_in, qkv, M, 3 * DD, DD);
    }

    // 2) Fused causal ALiBi attention
    {
        dim3 grid(LL / 64, BB * HH);
        attn_kernel<<<grid, 256>>>(qkv, att);
    }

    // 3) Output projection: [8192,1024] @ [1024,1024] + b_out  (tf32 mma.sync)
    {
        dim3 grid(DD / 128, M / 128);
        gemm_tf32_kernel<<<grid, 256, SMEM_BYTES>>>(att, wtout, b_out, out, M, DD, DD);
    }
}

// round 4
// speedup vs baseline: 1.9245x; 1.5922x over previous
#include <cuda_runtime.h>
#include <cstdint>

#define BB   2
#define LL   2048
#define DD   1024
#define HH   16
#define DHH  64

// Scratch (allocation-free: device globals)
__device__ float g_qkv[(size_t)BB * LL * 3 * DD];   // [B*L, 3D]
__device__ float g_att[(size_t)BB * LL * DD];       // [B*L, D] (b,l,h,dh)
__device__ float g_wtin[(size_t)3 * DD * DD];       // w_in^T  [3D, D]
__device__ float g_wtout[(size_t)DD * DD];          // w_out^T [D, D]

// ---------------------------------------------------------------------------
// helpers
// ---------------------------------------------------------------------------
__device__ __forceinline__ uint32_t f2tf32(float x) {
    uint32_t r;
    asm("cvt.rna.tf32.f32 %0, %1;" : "=r"(r) : "f"(x));
    return r;
}

__device__ __forceinline__ void mma_tf32(float* d, const uint32_t* a,
                                         const uint32_t* b) {
    asm volatile(
        "mma.sync.aligned.m16n8k8.row.col.f32.tf32.tf32.f32 "
        "{%0,%1,%2,%3}, {%4,%5,%6,%7}, {%8,%9}, {%0,%1,%2,%3};"
        : "+f"(d[0]), "+f"(d[1]), "+f"(d[2]), "+f"(d[3])
        : "r"(a[0]), "r"(a[1]), "r"(a[2]), "r"(a[3]),
          "r"(b[0]), "r"(b[1]));
}

// ---------------------------------------------------------------------------
// Transpose: out[c][r] = in[r][c].  in: [R, C] row-major.
// ---------------------------------------------------------------------------
__global__ __launch_bounds__(256) void transpose_kernel(
    const float* __restrict__ in, float* __restrict__ out, int R, int C)
{
    __shared__ float tile[32][33];
    int bx = blockIdx.x * 32, by = blockIdx.y * 32;
    int x = bx + threadIdx.x;
    #pragma unroll
    for (int i = 0; i < 32; i += 8) {
        int y = by + threadIdx.y + i;
        tile[threadIdx.y + i][threadIdx.x] = in[(size_t)y * C + x];
    }
    __syncthreads();
    int ox = by + threadIdx.x;
    #pragma unroll
    for (int i = 0; i < 32; i += 8) {
        int oy = bx + threadIdx.y + i;
        out[(size_t)oy * R + ox] = tile[threadIdx.x][threadIdx.y + i];
    }
}

// ---------------------------------------------------------------------------
// tf32 mma.sync GEMM: C[M,N] = A[M,K] @ Bt[N,K]^T + bias[N]
// CTA 128x128, BK=32, 8 warps (warp tile 64M x 32N, 4x4 m16n8k8 frags).
// ---------------------------------------------------------------------------
#define PADK 36   // 32 + 4 pad (floats per row)

__global__ __launch_bounds__(256) void gemm_tf32_kernel(
    const float* __restrict__ A, const float* __restrict__ Bt,
    const float* __restrict__ bias, float* __restrict__ C,
    int M, int N, int K)
{
    extern __shared__ uint32_t smem[];
    uint32_t* Abuf[2] = { smem,               smem + 128 * PADK };
    uint32_t* Bbuf[2] = { smem + 2 * 128 * PADK, smem + 3 * 128 * PADK };

    const int tid = threadIdx.x;
    const int wid = tid >> 5;
    const int lid = tid & 31;
    const int gid = lid >> 2;
    const int tig = lid & 3;

    const int bm = blockIdx.y * 128;
    const int bn = blockIdx.x * 128;

    const int warp_m = wid & 1;
    const int warp_n = wid >> 1;
    const int mbase = warp_m * 64;
    const int nbase = warp_n * 32;

    const int grow = tid >> 3;
    const int gc4  = tid & 7;

    float acc[4][4][4];
    #pragma unroll
    for (int i = 0; i < 4; i++)
        #pragma unroll
        for (int j = 0; j < 4; j++)
            #pragma unroll
            for (int e = 0; e < 4; e++) acc[i][j][e] = 0.0f;

    const int NC = K >> 5;

    float4 pa[4], pb[4];

    #pragma unroll
    for (int i = 0; i < 4; i++) {
        int r = grow + 32 * i;
        pa[i] = *(const float4*)(A  + (size_t)(bm + r) * K + gc4 * 4);
        pb[i] = *(const float4*)(Bt + (size_t)(bn + r) * K + gc4 * 4);
    }
    {
        uint32_t* As = Abuf[0];
        uint32_t* Bs = Bbuf[0];
        #pragma unroll
        for (int i = 0; i < 4; i++) {
            int r = grow + 32 * i;
            uint32_t* ap = As + r * PADK + gc4 * 4;
            ap[0] = f2tf32(pa[i].x); ap[1] = f2tf32(pa[i].y);
            ap[2] = f2tf32(pa[i].z); ap[3] = f2tf32(pa[i].w);
            uint32_t* bp = Bs + r * PADK + gc4 * 4;
            bp[0] = f2tf32(pb[i].x); bp[1] = f2tf32(pb[i].y);
            bp[2] = f2tf32(pb[i].z); bp[3] = f2tf32(pb[i].w);
        }
    }
    __syncthreads();

    for (int c = 0; c < NC; c++) {
        if (c + 1 < NC) {
            const float* Ab = A  + (size_t)bm * K + (c + 1) * 32;
            const float* Bb = Bt + (size_t)bn * K + (c + 1) * 32;
            #pragma unroll
            for (int i = 0; i < 4; i++) {
                int r = grow + 32 * i;
                pa[i] = *(const float4*)(Ab + (size_t)r * K + gc4 * 4);
                pb[i] = *(const float4*)(Bb + (size_t)r * K + gc4 * 4);
            }
        }

        {
            const uint32_t* As = Abuf[c & 1];
            const uint32_t* Bs = Bbuf[c & 1];
            #pragma unroll
            for (int ks = 0; ks < 4; ks++) {
                const int k0 = ks * 8;
                uint32_t af[4][4], bf[4][2];
                #pragma unroll
                for (int i = 0; i < 4; i++) {
                    const uint32_t* r0 = As + (mbase + i * 16 + gid) * PADK + k0 + tig;
                    const uint32_t* r1 = r0 + 8 * PADK;
                    af[i][0] = r0[0]; af[i][1] = r1[0];
                    af[i][2] = r0[4]; af[i][3] = r1[4];
                }
                #pragma unroll
                for (int j = 0; j < 4; j++) {
                    const uint32_t* r0 = Bs + (nbase + j * 8 + gid) * PADK + k0 + tig;
                    bf[j][0] = r0[0]; bf[j][1] = r0[4];
                }
                #pragma unroll
                for (int i = 0; i < 4; i++)
                    #pragma unroll
                    for (int j = 0; j < 4; j++)
                        mma_tf32(acc[i][j], af[i], bf[j]);
            }
        }

        if (c + 1 < NC) {
            uint32_t* As = Abuf[(c + 1) & 1];
            uint32_t* Bs = Bbuf[(c + 1) & 1];
            #pragma unroll
            for (int i = 0; i < 4; i++) {
                int r = grow + 32 * i;
                uint32_t* ap = As + r * PADK + gc4 * 4;
                ap[0] = f2tf32(pa[i].x); ap[1] = f2tf32(pa[i].y);
                ap[2] = f2tf32(pa[i].z); ap[3] = f2tf32(pa[i].w);
                uint32_t* bp = Bs + r * PADK + gc4 * 4;
                bp[0] = f2tf32(pb[i].x); bp[1] = f2tf32(pb[i].y);
                bp[2] = f2tf32(pb[i].z); bp[3] = f2tf32(pb[i].w);
            }
        }
        __syncthreads();
    }

    #pragma unroll
    for (int j = 0; j < 4; j++) {
        const int col = bn + nbase + j * 8 + 2 * tig;
        const float bi0 = __ldg(bias + col);
        const float bi1 = __ldg(bias + col + 1);
        #pragma unroll
        for (int i = 0; i < 4; i++) {
            const int row0 = bm + mbase + i * 16 + gid;
            float2 v0 = { acc[i][j][0] + bi0, acc[i][j][1] + bi1 };
            float2 v1 = { acc[i][j][2] + bi0, acc[i][j][3] + bi1 };
            *(float2*)(C + (size_t)row0 * N + col) = v0;
            *(float2*)(C + (size_t)(row0 + 8) * N + col) = v1;
        }
    }
}

// ---------------------------------------------------------------------------
// Fused causal ALiBi attention using m16n8k8 tf32 mma.sync.
// Q tile 128 x dh64; key chunks of 64. 8 warps, each owns 16 query rows
// across the full key width (softmax reductions stay in a quad).
// Grid: (16 q-tiles reversed, B*H). Block: 256 threads.
// ---------------------------------------------------------------------------
#define STRD 68    // words per smem row (conflict-free frag loads: 68%32==4)

__global__ __launch_bounds__(256, 2) void attn_mma_kernel(
    const float* __restrict__ qkv, float* __restrict__ out)
{
    extern __shared__ uint32_t sm[];
    uint32_t* Qs = sm;                       // [128][STRD] tf32
    uint32_t* Ks = Qs + 128 * STRD;          // [64][STRD]  tf32, [key][dh]
    uint32_t* Vt = Ks + 64 * STRD;           // [64][STRD]  tf32, [dh][key]
    uint32_t* Ps = Vt + 64 * STRD;           // [128][STRD] tf32

    const int tid = threadIdx.x;
    const int wid = tid >> 5;
    const int lid = tid & 31;
    const int gid = lid >> 2;
    const int tig = lid & 3;

    const int qt = (int)gridDim.x - 1 - (int)blockIdx.x;  // heavy tiles first
    const int bh = blockIdx.y;
    const int b  = bh >> 4;
    const int h  = bh & 15;

    const float slope = exp2f(-0.5f * (float)(h + 1));
    const float scale = 0.125f;   // 1/sqrt(64)

    const float* base = qkv + (size_t)b * LL * 3072 + h * 64;

    // Load Q tile: 128 rows x 64 dims, convert to tf32
    #pragma unroll
    for (int i = 0; i < 8; i++) {
        int idx = tid + i * 256;       // 0..2047 float4 slots
        int r = idx >> 4;
        int c4 = idx & 15;
        float4 v = *(const float4*)(base + (size_t)(qt * 128 + r) * 3072 + c4 * 4);
        uint32_t* p = Qs + r * STRD + c4 * 4;
        p[0] = f2tf32(v.x); p[1] = f2tf32(v.y);
        p[2] = f2tf32(v.z); p[3] = f2tf32(v.w);
    }

    const int mbase = wid * 16;
    const int row0g = qt * 128 + mbase + gid;   // this lane's first row

    float m0 = -1e30f, m1 = -1e30f, l0 = 0.0f, l1 = 0.0f;
    float O[8][4];
    #pragma unroll
    for (int j = 0; j < 8; j++)
        #pragma unroll
        for (int e = 0; e < 4; e++) O[j][e] = 0.0f;

    const int nkt = 2 * qt + 2;

    for (int kt = 0; kt < nkt; kt++) {
        __syncthreads();

        // Load K chunk [64][64] -> Ks[key][dh]; V -> transposed Vt[dh][key]
        #pragma unroll
        for (int i = 0; i < 4; i++) {
            int idx = tid + i * 256;   // 0..1023
            int r = idx >> 4;
            int c4 = idx & 15;
            const float* rp = base + (size_t)(kt * 64 + r) * 3072;
            float4 kv = *(const float4*)(rp + 1024 + c4 * 4);
            uint32_t* kp = Ks + r * STRD + c4 * 4;
            kp[0] = f2tf32(kv.x); kp[1] = f2tf32(kv.y);
            kp[2] = f2tf32(kv.z); kp[3] = f2tf32(kv.w);
            float4 vv = *(const float4*)(rp + 2048 + c4 * 4);
            Vt[(c4 * 4 + 0) * STRD + r] = f2tf32(vv.x);
            Vt[(c4 * 4 + 1) * STRD + r] = f2tf32(vv.y);
            Vt[(c4 * 4 + 2) * STRD + r] = f2tf32(vv.z);
            Vt[(c4 * 4 + 3) * STRD + r] = f2tf32(vv.w);
        }
        __syncthreads();

        // S = Q @ K^T   (warp: 16 rows x 64 keys = 8 n-frags)
        float s[8][4];
        #pragma unroll
        for (int j = 0; j < 8; j++)
            #pragma unroll
            for (int e = 0; e < 4; e++) s[j][e] = 0.0f;

        #pragma unroll
        for (int ks = 0; ks < 8; ks++) {
            uint32_t a[4];
            const uint32_t* qp = Qs + (mbase + gid) * STRD + ks * 8 + tig;
            a[0] = qp[0];            a[1] = qp[8 * STRD];
            a[2] = qp[4];            a[3] = qp[8 * STRD + 4];
            #pragma unroll
            for (int j = 0; j < 8; j++) {
                uint32_t bf[2];
                const uint32_t* kp = Ks + (j * 8 + gid) * STRD + ks * 8 + tig;
                bf[0] = kp[0]; bf[1] = kp[4];
                mma_tf32(s[j], a, bf);
            }
        }

        // scale + ALiBi + causal mask; per-row max (rows gid, gid+8)
        const int kc0 = kt * 64 + 2 * tig;
        float mv0 = -1e30f, mv1 = -1e30f;
        #pragma unroll
        for (int j = 0; j < 8; j++) {
            int kg0 = kc0 + j * 8;
            #pragma unroll
            for (int e = 0; e < 4; e++) {
                int kg = kg0 + (e & 1);
                int qg = row0g + ((e >> 1) << 3);
                float val = s[j][e] * scale + slope * (float)(kg - qg);
                val = (kg <= qg) ? val : -1e30f;
                s[j][e] = val;
                if (e < 2) mv0 = fmaxf(mv0, val);
                else       mv1 = fmaxf(mv1, val);
            }
        }
        mv0 = fmaxf(mv0, __shfl_xor_sync(0xffffffffu, mv0, 1));
        mv0 = fmaxf(mv0, __shfl_xor_sync(0xffffffffu, mv0, 2));
        mv1 = fmaxf(mv1, __shfl_xor_sync(0xffffffffu, mv1, 1));
        mv1 = fmaxf(mv1, __shfl_xor_sync(0xffffffffu, mv1, 2));

        const float mn0 = fmaxf(m0, mv0);
        const float mn1 = fmaxf(m1, mv1);

        float rs0 = 0.0f, rs1 = 0.0f;
        #pragma unroll
        for (int j = 0; j < 8; j++) {
            s[j][0] = __expf(s[j][0] - mn0);
            s[j][1] = __expf(s[j][1] - mn0);
            s[j][2] = __expf(s[j][2] - mn1);
            s[j][3] = __expf(s[j][3] - mn1);
            rs0 += s[j][0] + s[j][1];
            rs1 += s[j][2] + s[j][3];
        }
        rs0 += __shfl_xor_sync(0xffffffffu, rs0, 1);
        rs0 += __shfl_xor_sync(0xffffffffu, rs0, 2);
        rs1 += __shfl_xor_sync(0xffffffffu, rs1, 1);
        rs1 += __shfl_xor_sync(0xffffffffu, rs1, 2);

        const float c0 = __expf(m0 - mn0);
        const float c1 = __expf(m1 - mn1);
        l0 = l0 * c0 + rs0;
        l1 = l1 * c1 + rs1;
        m0 = mn0; m1 = mn1;
        #pragma unroll
        for (int j = 0; j < 8; j++) {
            O[j][0] *= c0; O[j][1] *= c0;
            O[j][2] *= c1; O[j][3] *= c1;
        }

        // Store P (warp-private rows; only warp-level ordering needed)
        #pragma unroll
        for (int j = 0; j < 8; j++) {
            uint32_t* pp = Ps + (mbase + gid) * STRD + j * 8 + 2 * tig;
            uint2 w0 = { f2tf32(s[j][0]), f2tf32(s[j][1]) };
            uint2 w1 = { f2tf32(s[j][2]), f2tf32(s[j][3]) };
            *(uint2*)pp = w0;
            *(uint2*)(pp + 8 * STRD) = w1;
        }
        __syncwarp();

        // O += P @ V
        #pragma unroll
        for (int ks = 0; ks < 8; ks++) {
            uint32_t a[4];
            const uint32_t* pp = Ps + (mbase + gid) * STRD + ks * 8 + tig;
            a[0] = pp[0];            a[1] = pp[8 * STRD];
            a[2] = pp[4];            a[3] = pp[8 * STRD + 4];
            #pragma unroll
            for (int j = 0; j < 8; j++) {
                uint32_t bf[2];
                const uint32_t* vp = Vt + (j * 8 + gid) * STRD + ks * 8 + tig;
                bf[0] = vp[0]; bf[1] = vp[4];
                mma_tf32(O[j], a, bf);
            }
        }
    }

    // Normalize and write out: out[b, row, h*64 + col]
    const float inv0 = 1.0f / l0;
    const float inv1 = 1.0f / l1;
    #pragma unroll
    for (int j = 0; j < 8; j++) {
        const int col = h * 64 + j * 8 + 2 * tig;
        float2 v0 = { O[j][0] * inv0, O[j][1] * inv0 };
        float2 v1 = { O[j][2] * inv1, O[j][3] * inv1 };
        *(float2*)(out + ((size_t)b * LL + row0g) * DD + col) = v0;
        *(float2*)(out + ((size_t)b * LL + row0g + 8) * DD + col) = v1;
    }
}

// ---------------------------------------------------------------------------
extern "C" void kernel_launch(void* const* d_in, const int* in_sizes, int n_in,
                              void* d_out, int out_size)
{
    const float* x     = (const float*)d_in[0];   // [B,L,D]
    const float* w_in  = (const float*)d_in[1];   // [D,3D]
    const float* b_in  = (const float*)d_in[2];   // [3D]
    const float* w_out = (const float*)d_in[3];   // [D,D]
    const float* b_out = (const float*)d_in[4];   // [D]
    float* out = (float*)d_out;                   // [B,L,D]

    float* qkv = nullptr;
    float* att = nullptr;
    float* wtin = nullptr;
    float* wtout = nullptr;
    cudaGetSymbolAddress((void**)&qkv, g_qkv);
    cudaGetSymbolAddress((void**)&att, g_att);
    cudaGetSymbolAddress((void**)&wtin, g_wtin);
    cudaGetSymbolAddress((void**)&wtout, g_wtout);

    const int M = BB * LL;   // 8192
    const int GEMM_SMEM = 4 * 128 * PADK * 4;          // 73728
    const int ATTN_SMEM = (128 + 64 + 64 + 128) * STRD * 4;  // 104448
    static bool attr_set = false;
    if (!attr_set) {
        cudaFuncSetAttribute(gemm_tf32_kernel,
                             cudaFuncAttributeMaxDynamicSharedMemorySize, GEMM_SMEM);
        cudaFuncSetAttribute(attn_mma_kernel,
                             cudaFuncAttributeMaxDynamicSharedMemorySize, ATTN_SMEM);
        attr_set = true;
    }

    // 0) Transpose weights to [N, K]
    {
        dim3 blk(32, 8);
        transpose_kernel<<<dim3(3 * DD / 32, DD / 32), blk>>>(w_in, wtin, DD, 3 * DD);
        transpose_kernel<<<dim3(DD / 32, DD / 32), blk>>>(w_out, wtout, DD, DD);
    }

    // 1) QKV projection
    {
        dim3 grid(3 * DD / 128, M / 128);
        gemm_tf32_kernel<<<grid, 256, GEMM_SMEM>>>(x, wtin, b_in, qkv, M, 3 * DD, DD);
    }

    // 2) Fused causal ALiBi attention (tensor-core)
    {
        dim3 grid(LL / 128, BB * HH);
        attn_mma_kernel<<<grid, 256, ATTN_SMEM>>>(qkv, att);
    }

    // 3) Output projection
    {
        dim3 grid(DD / 128, M / 128);
        gemm_tf32_kernel<<<grid, 256, GEMM_SMEM>>>(att, wtout, b_out, out, M, DD, DD);
    }
}

// round 5
// speedup vs baseline: 2.8506x; 1.4812x over previous
#include <cuda_runtime.h>
#include <cstdint>

#define BB   2
#define LL   2048
#define DD   1024
#define HH   16
#define DHH  64

// Scratch (allocation-free: device globals) — all values stored tf32-rounded
__device__ float g_xt[(size_t)BB * LL * DD];        // rounded x
__device__ float g_qkv[(size_t)BB * LL * 3 * DD];   // rounded qkv
__device__ float g_att[(size_t)BB * LL * DD];       // rounded attn out
__device__ float g_wtin[(size_t)3 * DD * DD];       // rounded w_in^T
__device__ float g_wtout[(size_t)DD * DD];          // rounded w_out^T

// ---------------------------------------------------------------------------
// helpers
// ---------------------------------------------------------------------------
__device__ __forceinline__ uint32_t f2tf32(float x) {
    uint32_t r;
    asm("cvt.rna.tf32.f32 %0, %1;" : "=r"(r) : "f"(x));
    return r;
}
__device__ __forceinline__ float roundtf(float x) {
    return __uint_as_float(f2tf32(x));
}

__device__ __forceinline__ void mma_tf32(float* d, const uint32_t* a,
                                         const uint32_t* b) {
    asm volatile(
        "mma.sync.aligned.m16n8k8.row.col.f32.tf32.tf32.f32 "
        "{%0,%1,%2,%3}, {%4,%5,%6,%7}, {%8,%9}, {%0,%1,%2,%3};"
        : "+f"(d[0]), "+f"(d[1]), "+f"(d[2]), "+f"(d[3])
        : "r"(a[0]), "r"(a[1]), "r"(a[2]), "r"(a[3]),
          "r"(b[0]), "r"(b[1]));
}

__device__ __forceinline__ uint32_t smem_u32(const void* p) {
    uint32_t a;
    asm("{ .reg .u64 t; cvta.to.shared.u64 t, %1; cvt.u32.u64 %0, t; }"
        : "=r"(a) : "l"(p));
    return a;
}

#define CP_ASYNC16(dst, src) \
    asm volatile("cp.async.cg.shared.global [%0], [%1], 16;" \
                 :: "r"(dst), "l"(src))
#define CP_COMMIT() asm volatile("cp.async.commit_group;")
#define CP_WAIT(n)  asm volatile("cp.async.wait_group %0;" :: "n"(n))

// ---------------------------------------------------------------------------
// Round a float buffer to tf32 precision (float4 grid-stride)
// ---------------------------------------------------------------------------
__global__ __launch_bounds__(256) void round_tf32_kernel(
    const float* __restrict__ in, float* __restrict__ out, int n4)
{
    int i = blockIdx.x * blockDim.x + threadIdx.x;
    if (i < n4) {
        float4 v = ((const float4*)in)[i];
        v.x = roundtf(v.x); v.y = roundtf(v.y);
        v.z = roundtf(v.z); v.w = roundtf(v.w);
        ((float4*)out)[i] = v;
    }
}

// ---------------------------------------------------------------------------
// Transpose + tf32 round: out[c][r] = tf32(in[r][c])
// ---------------------------------------------------------------------------
__global__ __launch_bounds__(256) void transpose_kernel(
    const float* __restrict__ in, float* __restrict__ out, int R, int C)
{
    __shared__ float tile[32][33];
    int bx = blockIdx.x * 32, by = blockIdx.y * 32;
    int x = bx + threadIdx.x;
    #pragma unroll
    for (int i = 0; i < 32; i += 8) {
        int y = by + threadIdx.y + i;
        tile[threadIdx.y + i][threadIdx.x] = in[(size_t)y * C + x];
    }
    __syncthreads();
    int ox = by + threadIdx.x;
    #pragma unroll
    for (int i = 0; i < 32; i += 8) {
        int oy = bx + threadIdx.y + i;
        out[(size_t)oy * R + ox] = roundtf(tile[threadIdx.x][threadIdx.y + i]);
    }
}

// ---------------------------------------------------------------------------
// tf32 mma.sync GEMM: C[M,N] = A[M,K] @ Bt[N,K]^T + bias[N]
// A, Bt pre-rounded to tf32. cp.async 2-stage pipeline, CTA 128x128, BK=32,
// 8 warps (warp tile 64M x 32N). round_out: write tf32-rounded C.
// ---------------------------------------------------------------------------
#define PADK 36   // 32 + 4 pad words per row; 36*4=144B rows keep 16B align

__global__ __launch_bounds__(256, 2) void gemm_tf32_kernel(
    const float* __restrict__ A, const float* __restrict__ Bt,
    const float* __restrict__ bias, float* __restrict__ C,
    int M, int N, int K, int round_out)
{
    extern __shared__ uint32_t smem[];
    const uint32_t sbase = smem_u32(smem);

    const int tid = threadIdx.x;
    const int wid = tid >> 5;
    const int lid = tid & 31;
    const int gid = lid >> 2;
    const int tig = lid & 3;

    const int bm = blockIdx.y * 128;
    const int bn = blockIdx.x * 128;

    const int warp_m = wid & 1;
    const int warp_n = wid >> 1;
    const int mbase = warp_m * 64;
    const int nbase = warp_n * 32;

    const int grow = tid >> 3;     // 0..31 (4 rows per thread, +32 apart)
    const int gc4  = tid & 7;      // 16B chunk within 32-float row

    float acc[4][4][4];
    #pragma unroll
    for (int i = 0; i < 4; i++)
        #pragma unroll
        for (int j = 0; j < 4; j++)
            #pragma unroll
            for (int e = 0; e < 4; e++) acc[i][j][e] = 0.0f;

    const int NC = K >> 5;

    // issue chunk c into buffer p
    auto issue = [&](int c, int p) {
        const float* Ab = A  + (size_t)bm * K + c * 32;
        const float* Bb = Bt + (size_t)bn * K + c * 32;
        const uint32_t aoff = sbase + (uint32_t)(p * 128 * PADK) * 4u;
        const uint32_t boff = sbase + (uint32_t)((2 + p) * 128 * PADK) * 4u;
        #pragma unroll
        for (int i = 0; i < 4; i++) {
            int r = grow + 32 * i;
            uint32_t d = (uint32_t)(r * PADK + gc4 * 4) * 4u;
            CP_ASYNC16(aoff + d, Ab + (size_t)r * K + gc4 * 4);
            CP_ASYNC16(boff + d, Bb + (size_t)r * K + gc4 * 4);
        }
    };

    issue(0, 0);
    CP_COMMIT();

    for (int c = 0; c < NC; c++) {
        if (c + 1 < NC) {
            issue(c + 1, (c + 1) & 1);
            CP_COMMIT();
            CP_WAIT(1);
        } else {
            CP_WAIT(0);
        }
        __syncthreads();

        const uint32_t* As = smem + (size_t)(c & 1) * 128 * PADK;
        const uint32_t* Bs = smem + (size_t)(2 + (c & 1)) * 128 * PADK;
        #pragma unroll
        for (int ks = 0; ks < 4; ks++) {
            const int k0 = ks * 8;
            uint32_t af[4][4], bf[4][2];
            #pragma unroll
            for (int i = 0; i < 4; i++) {
                const uint32_t* r0 = As + (mbase + i * 16 + gid) * PADK + k0 + tig;
                const uint32_t* r1 = r0 + 8 * PADK;
                af[i][0] = r0[0]; af[i][1] = r1[0];
                af[i][2] = r0[4]; af[i][3] = r1[4];
            }
            #pragma unroll
            for (int j = 0; j < 4; j++) {
                const uint32_t* r0 = Bs + (nbase + j * 8 + gid) * PADK + k0 + tig;
                bf[j][0] = r0[0]; bf[j][1] = r0[4];
            }
            #pragma unroll
            for (int i = 0; i < 4; i++)
                #pragma unroll
                for (int j = 0; j < 4; j++)
                    mma_tf32(acc[i][j], af[i], bf[j]);
        }
        __syncthreads();
    }

    #pragma unroll
    for (int j = 0; j < 4; j++) {
        const int col = bn + nbase + j * 8 + 2 * tig;
        const float bi0 = __ldg(bias + col);
        const float bi1 = __ldg(bias + col + 1);
        #pragma unroll
        for (int i = 0; i < 4; i++) {
            const int row0 = bm + mbase + i * 16 + gid;
            float2 v0 = { acc[i][j][0] + bi0, acc[i][j][1] + bi1 };
            float2 v1 = { acc[i][j][2] + bi0, acc[i][j][3] + bi1 };
            if (round_out) {
                v0.x = roundtf(v0.x); v0.y = roundtf(v0.y);
                v1.x = roundtf(v1.x); v1.y = roundtf(v1.y);
            }
            *(float2*)(C + (size_t)row0 * N + col) = v0;
            *(float2*)(C + (size_t)(row0 + 8) * N + col) = v1;
        }
    }
}

// ---------------------------------------------------------------------------
// Fused causal ALiBi attention using m16n8k8 tf32 mma.sync.
// qkv is pre-rounded tf32 -> smem fills are raw bit copies.
// Q tile 128 x dh64; key chunks of 64. 8 warps x 16 query rows.
// ---------------------------------------------------------------------------
#define STRD 68

__global__ __launch_bounds__(256, 2) void attn_mma_kernel(
    const float* __restrict__ qkv, float* __restrict__ out)
{
    extern __shared__ uint32_t sm[];
    uint32_t* Qs = sm;                       // [128][STRD]
    uint32_t* Ks = Qs + 128 * STRD;          // [64][STRD]  [key][dh]
    uint32_t* Vt = Ks + 64 * STRD;           // [64][STRD]  [dh][key]
    uint32_t* Ps = Vt + 64 * STRD;           // [128][STRD]

    const int tid = threadIdx.x;
    const int wid = tid >> 5;
    const int lid = tid & 31;
    const int gid = lid >> 2;
    const int tig = lid & 3;

    const int qt = (int)gridDim.x - 1 - (int)blockIdx.x;
    const int bh = blockIdx.y;
    const int b  = bh >> 4;
    const int h  = bh & 15;

    const float slope = exp2f(-0.5f * (float)(h + 1));
    const float scale = 0.125f;

    const uint32_t* base =
        (const uint32_t*)qkv + (size_t)b * LL * 3072 + h * 64;

    // Q tile: raw copy (already tf32)
    #pragma unroll
    for (int i = 0; i < 8; i++) {
        int idx = tid + i * 256;
        int r = idx >> 4;
        int c4 = idx & 15;
        uint4 v = *(const uint4*)(base + (size_t)(qt * 128 + r) * 3072 + c4 * 4);
        *(uint4*)(Qs + r * STRD + c4 * 4) = v;
    }

    const int mbase = wid * 16;
    const int row0g = qt * 128 + mbase + gid;

    float m0 = -1e30f, m1 = -1e30f, l0 = 0.0f, l1 = 0.0f;
    float O[8][4];
    #pragma unroll
    for (int j = 0; j < 8; j++)
        #pragma unroll
        for (int e = 0; e < 4; e++) O[j][e] = 0.0f;

    const int nkt = 2 * qt + 2;

    for (int kt = 0; kt < nkt; kt++) {
        __syncthreads();

        #pragma unroll
        for (int i = 0; i < 4; i++) {
            int idx = tid + i * 256;
            int r = idx >> 4;
            int c4 = idx & 15;
            const uint32_t* rp = base + (size_t)(kt * 64 + r) * 3072;
            uint4 kv = *(const uint4*)(rp + 1024 + c4 * 4);
            *(uint4*)(Ks + r * STRD + c4 * 4) = kv;
            uint4 vv = *(const uint4*)(rp + 2048 + c4 * 4);
            Vt[(c4 * 4 + 0) * STRD + r] = vv.x;
            Vt[(c4 * 4 + 1) * STRD + r] = vv.y;
            Vt[(c4 * 4 + 2) * STRD + r] = vv.z;
            Vt[(c4 * 4 + 3) * STRD + r] = vv.w;
        }
        __syncthreads();

        float s[8][4];
        #pragma unroll
        for (int j = 0; j < 8; j++)
            #pragma unroll
            for (int e = 0; e < 4; e++) s[j][e] = 0.0f;

        #pragma unroll
        for (int ks = 0; ks < 8; ks++) {
            uint32_t a[4];
            const uint32_t* qp = Qs + (mbase + gid) * STRD + ks * 8 + tig;
            a[0] = qp[0];            a[1] = qp[8 * STRD];
            a[2] = qp[4];            a[3] = qp[8 * STRD + 4];
            #pragma unroll
            for (int j = 0; j < 8; j++) {
                uint32_t bf[2];
                const uint32_t* kp = Ks + (j * 8 + gid) * STRD + ks * 8 + tig;
                bf[0] = kp[0]; bf[1] = kp[4];
                mma_tf32(s[j], a, bf);
            }
        }

        const int kc0 = kt * 64 + 2 * tig;
        float mv0 = -1e30f, mv1 = -1e30f;
        #pragma unroll
        for (int j = 0; j < 8; j++) {
            int kg0 = kc0 + j * 8;
            #pragma unroll
            for (int e = 0; e < 4; e++) {
                int kg = kg0 + (e & 1);
                int qg = row0g + ((e >> 1) << 3);
                float val = s[j][e] * scale + slope * (float)(kg - qg);
                val = (kg <= qg) ? val : -1e30f;
                s[j][e] = val;
                if (e < 2) mv0 = fmaxf(mv0, val);
                else       mv1 = fmaxf(mv1, val);
            }
        }
        mv0 = fmaxf(mv0, __shfl_xor_sync(0xffffffffu, mv0, 1));
        mv0 = fmaxf(mv0, __shfl_xor_sync(0xffffffffu, mv0, 2));
        mv1 = fmaxf(mv1, __shfl_xor_sync(0xffffffffu, mv1, 1));
        mv1 = fmaxf(mv1, __shfl_xor_sync(0xffffffffu, mv1, 2));

        const float mn0 = fmaxf(m0, mv0);
        const float mn1 = fmaxf(m1, mv1);

        float rs0 = 0.0f, rs1 = 0.0f;
        #pragma unroll
        for (int j = 0; j < 8; j++) {
            s[j][0] = __expf(s[j][0] - mn0);
            s[j][1] = __expf(s[j][1] - mn0);
            s[j][2] = __expf(s[j][2] - mn1);
            s[j][3] = __expf(s[j][3] - mn1);
            rs0 += s[j][0] + s[j][1];
            rs1 += s[j][2] + s[j][3];
        }
        rs0 += __shfl_xor_sync(0xffffffffu, rs0, 1);
        rs0 += __shfl_xor_sync(0xffffffffu, rs0, 2);
        rs1 += __shfl_xor_sync(0xffffffffu, rs1, 1);
        rs1 += __shfl_xor_sync(0xffffffffu, rs1, 2);

        const float c0 = __expf(m0 - mn0);
        const float c1 = __expf(m1 - mn1);
        l0 = l0 * c0 + rs0;
        l1 = l1 * c1 + rs1;
        m0 = mn0; m1 = mn1;
        #pragma unroll
        for (int j = 0; j < 8; j++) {
            O[j][0] *= c0; O[j][1] *= c0;
            O[j][2] *= c1; O[j][3] *= c1;
        }

        #pragma unroll
        for (int j = 0; j < 8; j++) {
            uint32_t* pp = Ps + (mbase + gid) * STRD + j * 8 + 2 * tig;
            uint2 w0 = { f2tf32(s[j][0]), f2tf32(s[j][1]) };
            uint2 w1 = { f2tf32(s[j][2]), f2tf32(s[j][3]) };
            *(uint2*)pp = w0;
            *(uint2*)(pp + 8 * STRD) = w1;
        }
        __syncwarp();

        #pragma unroll
        for (int ks = 0; ks < 8; ks++) {
            uint32_t a[4];
            const uint32_t* pp = Ps + (mbase + gid) * STRD + ks * 8 + tig;
            a[0] = pp[0];            a[1] = pp[8 * STRD];
            a[2] = pp[4];            a[3] = pp[8 * STRD + 4];
            #pragma unroll
            for (int j = 0; j < 8; j++) {
                uint32_t bf[2];
                const uint32_t* vp = Vt + (j * 8 + gid) * STRD + ks * 8 + tig;
                bf[0] = vp[0]; bf[1] = vp[4];
                mma_tf32(O[j], a, bf);
            }
        }
    }

    // Write tf32-rounded output (consumed by GEMM2 as tf32 A operand)
    const float inv0 = 1.0f / l0;
    const float inv1 = 1.0f / l1;
    #pragma unroll
    for (int j = 0; j < 8; j++) {
        const int col = h * 64 + j * 8 + 2 * tig;
        float2 v0 = { roundtf(O[j][0] * inv0), roundtf(O[j][1] * inv0) };
        float2 v1 = { roundtf(O[j][2] * inv1), roundtf(O[j][3] * inv1) };
        *(float2*)(out + ((size_t)b * LL + row0g) * DD + col) = v0;
        *(float2*)(out + ((size_t)b * LL + row0g + 8) * DD + col) = v1;
    }
}

// ---------------------------------------------------------------------------
extern "C" void kernel_launch(void* const* d_in, const int* in_sizes, int n_in,
                              void* d_out, int out_size)
{
    const float* x     = (const float*)d_in[0];
    const float* w_in  = (const float*)d_in[1];
    const float* b_in  = (const float*)d_in[2];
    const float* w_out = (const float*)d_in[3];
    const float* b_out = (const float*)d_in[4];
    float* out = (float*)d_out;

    float *xt, *qkv, *att, *wtin, *wtout;
    cudaGetSymbolAddress((void**)&xt, g_xt);
    cudaGetSymbolAddress((void**)&qkv, g_qkv);
    cudaGetSymbolAddress((void**)&att, g_att);
    cudaGetSymbolAddress((void**)&wtin, g_wtin);
    cudaGetSymbolAddress((void**)&wtout, g_wtout);

    const int M = BB * LL;
    const int GEMM_SMEM = 4 * 128 * PADK * 4;                 // 73728
    const int ATTN_SMEM = (128 + 64 + 64 + 128) * STRD * 4;   // 104448
    static bool attr_set = false;
    if (!attr_set) {
        cudaFuncSetAttribute(gemm_tf32_kernel,
                             cudaFuncAttributeMaxDynamicSharedMemorySize, GEMM_SMEM);
        cudaFuncSetAttribute(attn_mma_kernel,
                             cudaFuncAttributeMaxDynamicSharedMemorySize, ATTN_SMEM);
        attr_set = true;
    }

    // 0) Round x; transpose+round weights
    {
        int n4 = M * DD / 4;
        round_tf32_kernel<<<(n4 + 255) / 256, 256>>>(x, xt, n4);
        dim3 blk(32, 8);
        transpose_kernel<<<dim3(3 * DD / 32, DD / 32), blk>>>(w_in, wtin, DD, 3 * DD);
        transpose_kernel<<<dim3(DD / 32, DD / 32), blk>>>(w_out, wtout, DD, DD);
    }

    // 1) QKV projection (writes tf32-rounded qkv)
    {
        dim3 grid(3 * DD / 128, M / 128);
        gemm_tf32_kernel<<<grid, 256, GEMM_SMEM>>>(xt, wtin, b_in, qkv,
                                                   M, 3 * DD, DD, 1);
    }

    // 2) Fused causal ALiBi attention (writes tf32-rounded att)
    {
        dim3 grid(LL / 128, BB * HH);
        attn_mma_kernel<<<grid, 256, ATTN_SMEM>>>(qkv, att);
    }

    // 3) Output projection (final fp32)
    {
        dim3 grid(DD / 128, M / 128);
        gemm_tf32_kernel<<<grid, 256, GEMM_SMEM>>>(att, wtout, b_out, out,
                                                   M, DD, DD, 0);
    }
}

// round 6
// speedup vs baseline: 3.0792x; 1.0802x over previous
#include <cuda_runtime.h>
#include <cstdint>

#define BB   2
#define LL   2048
#define DD   1024
#define HH   16
#define DHH  64

// Scratch (allocation-free: device globals) — all values stored tf32-rounded
__device__ float g_xt[(size_t)BB * LL * DD];
__device__ float g_qkv[(size_t)BB * LL * 3 * DD];
__device__ float g_att[(size_t)BB * LL * DD];
__device__ float g_wtin[(size_t)3 * DD * DD];
__device__ float g_wtout[(size_t)DD * DD];

// ---------------------------------------------------------------------------
// helpers
// ---------------------------------------------------------------------------
__device__ __forceinline__ uint32_t f2tf32(float x) {
    uint32_t r;
    asm("cvt.rna.tf32.f32 %0, %1;" : "=r"(r) : "f"(x));
    return r;
}
__device__ __forceinline__ float roundtf(float x) {
    return __uint_as_float(f2tf32(x));
}

__device__ __forceinline__ void mma_tf32(float* d, const uint32_t* a,
                                         const uint32_t* b) {
    asm volatile(
        "mma.sync.aligned.m16n8k8.row.col.f32.tf32.tf32.f32 "
        "{%0,%1,%2,%3}, {%4,%5,%6,%7}, {%8,%9}, {%0,%1,%2,%3};"
        : "+f"(d[0]), "+f"(d[1]), "+f"(d[2]), "+f"(d[3])
        : "r"(a[0]), "r"(a[1]), "r"(a[2]), "r"(a[3]),
          "r"(b[0]), "r"(b[1]));
}

__device__ __forceinline__ uint32_t smem_u32(const void* p) {
    uint32_t a;
    asm("{ .reg .u64 t; cvta.to.shared.u64 t, %1; cvt.u32.u64 %0, t; }"
        : "=r"(a) : "l"(p));
    return a;
}

#define CP_ASYNC16(dst, src) \
    asm volatile("cp.async.cg.shared.global [%0], [%1], 16;" \
                 :: "r"(dst), "l"(src))
#define CP_COMMIT() asm volatile("cp.async.commit_group;")
#define CP_WAIT(n)  asm volatile("cp.async.wait_group %0;" :: "n"(n))

// ---------------------------------------------------------------------------
// Round a float buffer to tf32 precision
// ---------------------------------------------------------------------------
__global__ __launch_bounds__(256) void round_tf32_kernel(
    const float* __restrict__ in, float* __restrict__ out, int n4)
{
    int i = blockIdx.x * blockDim.x + threadIdx.x;
    if (i < n4) {
        float4 v = ((const float4*)in)[i];
        v.x = roundtf(v.x); v.y = roundtf(v.y);
        v.z = roundtf(v.z); v.w = roundtf(v.w);
        ((float4*)out)[i] = v;
    }
}

// ---------------------------------------------------------------------------
// Transpose + tf32 round: out[c][r] = tf32(in[r][c])
// ---------------------------------------------------------------------------
__global__ __launch_bounds__(256) void transpose_kernel(
    const float* __restrict__ in, float* __restrict__ out, int R, int C)
{
    __shared__ float tile[32][33];
    int bx = blockIdx.x * 32, by = blockIdx.y * 32;
    int x = bx + threadIdx.x;
    #pragma unroll
    for (int i = 0; i < 32; i += 8) {
        int y = by + threadIdx.y + i;
        tile[threadIdx.y + i][threadIdx.x] = in[(size_t)y * C + x];
    }
    __syncthreads();
    int ox = by + threadIdx.x;
    #pragma unroll
    for (int i = 0; i < 32; i += 8) {
        int oy = bx + threadIdx.y + i;
        out[(size_t)oy * R + ox] = roundtf(tile[threadIdx.x][threadIdx.y + i]);
    }
}

// ---------------------------------------------------------------------------
// tf32 mma.sync GEMM: C[M,N] = A[M,K] @ Bt[N,K]^T + bias[N]
// 3-stage cp.async pipeline, ONE __syncthreads per 32-K chunk.
// CTA 128x128, 8 warps (warp tile 64M x 32N).
// ---------------------------------------------------------------------------
#define PADK 36

__global__ __launch_bounds__(256, 2) void gemm_tf32_kernel(
    const float* __restrict__ A, const float* __restrict__ Bt,
    const float* __restrict__ bias, float* __restrict__ C,
    int M, int N, int K, int round_out)
{
    extern __shared__ uint32_t smem[];
    const uint32_t sbase = smem_u32(smem);

    const int tid = threadIdx.x;
    const int wid = tid >> 5;
    const int lid = tid & 31;
    const int gid = lid >> 2;
    const int tig = lid & 3;

    const int bm = blockIdx.y * 128;
    const int bn = blockIdx.x * 128;

    const int mbase = (wid & 1) * 64;
    const int nbase = (wid >> 1) * 32;

    const int grow = tid >> 3;
    const int gc4  = tid & 7;

    float acc[4][4][4];
    #pragma unroll
    for (int i = 0; i < 4; i++)
        #pragma unroll
        for (int j = 0; j < 4; j++)
            #pragma unroll
            for (int e = 0; e < 4; e++) acc[i][j][e] = 0.0f;

    const int NC = K >> 5;
    constexpr uint32_t STG = 128 * PADK * 4;   // bytes per operand stage

    auto issue = [&](int c) {
        const int p = c % 3;
        const float* Ab = A  + (size_t)bm * K + c * 32;
        const float* Bb = Bt + (size_t)bn * K + c * 32;
        const uint32_t aoff = sbase + (uint32_t)p * STG;
        const uint32_t boff = sbase + (uint32_t)(3 + p) * STG;
        #pragma unroll
        for (int i = 0; i < 4; i++) {
            int r = grow + 32 * i;
            uint32_t d = (uint32_t)(r * PADK + gc4 * 4) * 4u;
            CP_ASYNC16(aoff + d, Ab + (size_t)r * K + gc4 * 4);
            CP_ASYNC16(boff + d, Bb + (size_t)r * K + gc4 * 4);
        }
        CP_COMMIT();
    };

    issue(0);
    issue(1);

    for (int c = 0; c < NC; c++) {
        if (c + 2 < NC) { CP_WAIT(1); } else { CP_WAIT(0); }
        __syncthreads();
        if (c + 2 < NC) issue(c + 2);

        const uint32_t* As = smem + (size_t)(c % 3) * 128 * PADK;
        const uint32_t* Bs = smem + (size_t)(3 + c % 3) * 128 * PADK;
        #pragma unroll
        for (int ks = 0; ks < 4; ks++) {
            const int k0 = ks * 8;
            uint32_t af[4][4], bf[4][2];
            #pragma unroll
            for (int i = 0; i < 4; i++) {
                const uint32_t* r0 = As + (mbase + i * 16 + gid) * PADK + k0 + tig;
                const uint32_t* r1 = r0 + 8 * PADK;
                af[i][0] = r0[0]; af[i][1] = r1[0];
                af[i][2] = r0[4]; af[i][3] = r1[4];
            }
            #pragma unroll
            for (int j = 0; j < 4; j++) {
                const uint32_t* r0 = Bs + (nbase + j * 8 + gid) * PADK + k0 + tig;
                bf[j][0] = r0[0]; bf[j][1] = r0[4];
            }
            #pragma unroll
            for (int i = 0; i < 4; i++)
                #pragma unroll
                for (int j = 0; j < 4; j++)
                    mma_tf32(acc[i][j], af[i], bf[j]);
        }
    }

    #pragma unroll
    for (int j = 0; j < 4; j++) {
        const int col = bn + nbase + j * 8 + 2 * tig;
        const float bi0 = __ldg(bias + col);
        const float bi1 = __ldg(bias + col + 1);
        #pragma unroll
        for (int i = 0; i < 4; i++) {
            const int row0 = bm + mbase + i * 16 + gid;
            float2 v0 = { acc[i][j][0] + bi0, acc[i][j][1] + bi1 };
            float2 v1 = { acc[i][j][2] + bi0, acc[i][j][3] + bi1 };
            if (round_out) {
                v0.x = roundtf(v0.x); v0.y = roundtf(v0.y);
                v1.x = roundtf(v1.x); v1.y = roundtf(v1.y);
            }
            *(float2*)(C + (size_t)row0 * N + col) = v0;
            *(float2*)(C + (size_t)(row0 + 8) * N + col) = v1;
        }
    }
}

// ---------------------------------------------------------------------------
// Fused causal ALiBi attention, m16n8k8 tf32 mma.sync.
// Q/K/P smem stride 68 (conflict-free for row-indexed frags);
// V row-major stride 72 (conflict-free for k-indexed B frags -> no transpose).
// Masking only on the 2 diagonal chunks.
// ---------------------------------------------------------------------------
#define STRD 68
#define VSTR 72

__global__ __launch_bounds__(256, 2) void attn_mma_kernel(
    const float* __restrict__ qkv, float* __restrict__ out)
{
    extern __shared__ uint32_t sm[];
    uint32_t* Qs = sm;                        // [128][STRD]
    uint32_t* Ks = Qs + 128 * STRD;           // [64][STRD]   [key][dh]
    uint32_t* Vs = Ks + 64 * STRD;            // [64][VSTR]   [key][dh]
    uint32_t* Ps = Vs + 64 * VSTR;            // [128][STRD]

    const int tid = threadIdx.x;
    const int wid = tid >> 5;
    const int lid = tid & 31;
    const int gid = lid >> 2;
    const int tig = lid & 3;

    const int qt = (int)gridDim.x - 1 - (int)blockIdx.x;
    const int bh = blockIdx.y;
    const int b  = bh >> 4;
    const int h  = bh & 15;

    const float slope = exp2f(-0.5f * (float)(h + 1));
    const float scale = 0.125f;

    const float* base = qkv + (size_t)b * LL * 3072 + h * 64;
    const uint32_t qsb = smem_u32(Qs);
    const uint32_t ksb = smem_u32(Ks);
    const uint32_t vsb = smem_u32(Vs);

    // Q tile via cp.async (consumed after first chunk's wait+sync)
    #pragma unroll
    for (int i = 0; i < 8; i++) {
        int idx = tid + i * 256;
        int r = idx >> 4;
        int c4 = idx & 15;
        CP_ASYNC16(qsb + (uint32_t)(r * STRD + c4 * 4) * 4u,
                   base + (size_t)(qt * 128 + r) * 3072 + c4 * 4);
    }
    CP_COMMIT();

    const int mbase = wid * 16;
    const int row0g = qt * 128 + mbase + gid;

    float m0 = -1e30f, m1 = -1e30f, l0 = 0.0f, l1 = 0.0f;
    float O[8][4];
    #pragma unroll
    for (int j = 0; j < 8; j++)
        #pragma unroll
        for (int e = 0; e < 4; e++) O[j][e] = 0.0f;

    const float sq0 = slope * (float)row0g;
    const float sq1 = slope * (float)(row0g + 8);

    auto do_chunk = [&](int kt, bool MASKED) {
        __syncthreads();   // all warps done reading Ks/Vs/Qs(first iter ok)

        #pragma unroll
        for (int i = 0; i < 4; i++) {
            int idx = tid + i * 256;
            int r = idx >> 4;
            int c4 = idx & 15;
            const float* rp = base + (size_t)(kt * 64 + r) * 3072;
            CP_ASYNC16(ksb + (uint32_t)(r * STRD + c4 * 4) * 4u, rp + 1024 + c4 * 4);
            CP_ASYNC16(vsb + (uint32_t)(r * VSTR + c4 * 4) * 4u, rp + 2048 + c4 * 4);
        }
        CP_COMMIT();
        CP_WAIT(0);
        __syncthreads();

        // S = Q @ K^T
        float s[8][4];
        #pragma unroll
        for (int j = 0; j < 8; j++)
            #pragma unroll
            for (int e = 0; e < 4; e++) s[j][e] = 0.0f;

        #pragma unroll
        for (int ks = 0; ks < 8; ks++) {
            uint32_t a[4];
            const uint32_t* qp = Qs + (mbase + gid) * STRD + ks * 8 + tig;
            a[0] = qp[0];            a[1] = qp[8 * STRD];
            a[2] = qp[4];            a[3] = qp[8 * STRD + 4];
            #pragma unroll
            for (int j = 0; j < 8; j++) {
                uint32_t bf[2];
                const uint32_t* kp = Ks + (j * 8 + gid) * STRD + ks * 8 + tig;
                bf[0] = kp[0]; bf[1] = kp[4];
                mma_tf32(s[j], a, bf);
            }
        }

        // scale + ALiBi (+ causal mask only on diagonal chunks)
        const int kc0 = kt * 64 + 2 * tig;
        float mv0 = -1e30f, mv1 = -1e30f;
        #pragma unroll
        for (int j = 0; j < 8; j++) {
            const float sk0 = slope * (float)(kc0 + j * 8);
            const float sk1 = sk0 + slope;
            float v0 = s[j][0] * scale + sk0 - sq0;
            float v1 = s[j][1] * scale + sk1 - sq0;
            float v2 = s[j][2] * scale + sk0 - sq1;
            float v3 = s[j][3] * scale + sk1 - sq1;
            if (MASKED) {
                int kg0 = kc0 + j * 8, kg1 = kg0 + 1;
                v0 = (kg0 <= row0g)     ? v0 : -1e30f;
                v1 = (kg1 <= row0g)     ? v1 : -1e30f;
                v2 = (kg0 <= row0g + 8) ? v2 : -1e30f;
                v3 = (kg1 <= row0g + 8) ? v3 : -1e30f;
            }
            s[j][0] = v0; s[j][1] = v1; s[j][2] = v2; s[j][3] = v3;
            mv0 = fmaxf(mv0, fmaxf(v0, v1));
            mv1 = fmaxf(mv1, fmaxf(v2, v3));
        }
        mv0 = fmaxf(mv0, __shfl_xor_sync(0xffffffffu, mv0, 1));
        mv0 = fmaxf(mv0, __shfl_xor_sync(0xffffffffu, mv0, 2));
        mv1 = fmaxf(mv1, __shfl_xor_sync(0xffffffffu, mv1, 1));
        mv1 = fmaxf(mv1, __shfl_xor_sync(0xffffffffu, mv1, 2));

        const float mn0 = fmaxf(m0, mv0);
        const float mn1 = fmaxf(m1, mv1);

        float rs0 = 0.0f, rs1 = 0.0f;
        #pragma unroll
        for (int j = 0; j < 8; j++) {
            s[j][0] = __expf(s[j][0] - mn0);
            s[j][1] = __expf(s[j][1] - mn0);
            s[j][2] = __expf(s[j][2] - mn1);
            s[j][3] = __expf(s[j][3] - mn1);
            rs0 += s[j][0] + s[j][1];
            rs1 += s[j][2] + s[j][3];
        }
        rs0 += __shfl_xor_sync(0xffffffffu, rs0, 1);
        rs0 += __shfl_xor_sync(0xffffffffu, rs0, 2);
        rs1 += __shfl_xor_sync(0xffffffffu, rs1, 1);
        rs1 += __shfl_xor_sync(0xffffffffu, rs1, 2);

        const float c0 = __expf(m0 - mn0);
        const float c1 = __expf(m1 - mn1);
        l0 = l0 * c0 + rs0;
        l1 = l1 * c1 + rs1;
        m0 = mn0; m1 = mn1;
        #pragma unroll
        for (int j = 0; j < 8; j++) {
            O[j][0] *= c0; O[j][1] *= c0;
            O[j][2] *= c1; O[j][3] *= c1;
        }

        // P -> smem (warp-private rows)
        #pragma unroll
        for (int j = 0; j < 8; j++) {
            uint32_t* pp = Ps + (mbase + gid) * STRD + j * 8 + 2 * tig;
            uint2 w0 = { f2tf32(s[j][0]), f2tf32(s[j][1]) };
            uint2 w1 = { f2tf32(s[j][2]), f2tf32(s[j][3]) };
            *(uint2*)pp = w0;
            *(uint2*)(pp + 8 * STRD) = w1;
        }
        __syncwarp();

        // O += P @ V   (B frags straight from row-major Vs, stride 72)
        #pragma unroll
        for (int ks = 0; ks < 8; ks++) {
            uint32_t a[4];
            const uint32_t* pp = Ps + (mbase + gid) * STRD + ks * 8 + tig;
            a[0] = pp[0];            a[1] = pp[8 * STRD];
            a[2] = pp[4];            a[3] = pp[8 * STRD + 4];
            #pragma unroll
            for (int j = 0; j < 8; j++) {
                uint32_t bf[2];
                const uint32_t* vp = Vs + (ks * 8 + tig) * VSTR + j * 8 + gid;
                bf[0] = vp[0]; bf[1] = vp[4 * VSTR];
                mma_tf32(O[j], a, bf);
            }
        }
    };

    const int nfull = 2 * qt;
    for (int kt = 0; kt < nfull; kt++) do_chunk(kt, false);
    do_chunk(nfull, true);
    do_chunk(nfull + 1, true);

    const float inv0 = 1.0f / l0;
    const float inv1 = 1.0f / l1;
    #pragma unroll
    for (int j = 0; j < 8; j++) {
        const int col = h * 64 + j * 8 + 2 * tig;
        float2 v0 = { roundtf(O[j][0] * inv0), roundtf(O[j][1] * inv0) };
        float2 v1 = { roundtf(O[j][2] * inv1), roundtf(O[j][3] * inv1) };
        *(float2*)(out + ((size_t)b * LL + row0g) * DD + col) = v0;
        *(float2*)(out + ((size_t)b * LL + row0g + 8) * DD + col) = v1;
    }
}

// ---------------------------------------------------------------------------
extern "C" void kernel_launch(void* const* d_in, const int* in_sizes, int n_in,
                              void* d_out, int out_size)
{
    const float* x     = (const float*)d_in[0];
    const float* w_in  = (const float*)d_in[1];
    const float* b_in  = (const float*)d_in[2];
    const float* w_out = (const float*)d_in[3];
    const float* b_out = (const float*)d_in[4];
    float* out = (float*)d_out;

    float *xt, *qkv, *att, *wtin, *wtout;
    cudaGetSymbolAddress((void**)&xt, g_xt);
    cudaGetSymbolAddress((void**)&qkv, g_qkv);
    cudaGetSymbolAddress((void**)&att, g_att);
    cudaGetSymbolAddress((void**)&wtin, g_wtin);
    cudaGetSymbolAddress((void**)&wtout, g_wtout);

    const int M = BB * LL;
    const int GEMM_SMEM = 6 * 128 * PADK * 4;                        // 110592
    const int ATTN_SMEM = (128 * STRD + 64 * STRD + 64 * VSTR + 128 * STRD) * 4; // 105472
    static bool attr_set = false;
    if (!attr_set) {
        cudaFuncSetAttribute(gemm_tf32_kernel,
                             cudaFuncAttributeMaxDynamicSharedMemorySize, GEMM_SMEM);
        cudaFuncSetAttribute(attn_mma_kernel,
                             cudaFuncAttributeMaxDynamicSharedMemorySize, ATTN_SMEM);
        attr_set = true;
    }

    // 0) Round x; transpose+round weights
    {
        int n4 = M * DD / 4;
        round_tf32_kernel<<<(n4 + 255) / 256, 256>>>(x, xt, n4);
        dim3 blk(32, 8);
        transpose_kernel<<<dim3(3 * DD / 32, DD / 32), blk>>>(w_in, wtin, DD, 3 * DD);
        transpose_kernel<<<dim3(DD / 32, DD / 32), blk>>>(w_out, wtout, DD, DD);
    }

    // 1) QKV projection (tf32-rounded output)
    {
        dim3 grid(3 * DD / 128, M / 128);
        gemm_tf32_kernel<<<grid, 256, GEMM_SMEM>>>(xt, wtin, b_in, qkv,
                                                   M, 3 * DD, DD, 1);
    }

    // 2) Fused causal ALiBi attention (tf32-rounded output)
    {
        dim3 grid(LL / 128, BB * HH);
        attn_mma_kernel<<<grid, 256, ATTN_SMEM>>>(qkv, att);
    }

    // 3) Output projection (final fp32)
    {
        dim3 grid(DD / 128, M / 128);
        gemm_tf32_kernel<<<grid, 256, GEMM_SMEM>>>(att, wtout, b_out, out,
                                                   M, DD, DD, 0);
    }
}

// round 7
// speedup vs baseline: 3.3664x; 1.0933x over previous
#include <cuda_runtime.h>
#include <cstdint>

#define BB   2
#define LL   2048
#define DD   1024
#define HH   16
#define DHH  64

// Scratch (allocation-free: device globals) — all values stored tf32-rounded
__device__ float g_xt[(size_t)BB * LL * DD];
__device__ float g_qkv[(size_t)BB * LL * 3 * DD];
__device__ float g_att[(size_t)BB * LL * DD];
__device__ float g_wtin[(size_t)3 * DD * DD];
__device__ float g_wtout[(size_t)DD * DD];

// ---------------------------------------------------------------------------
// helpers
// ---------------------------------------------------------------------------
__device__ __forceinline__ uint32_t f2tf32(float x) {
    uint32_t r;
    asm("cvt.rna.tf32.f32 %0, %1;" : "=r"(r) : "f"(x));
    return r;
}
__device__ __forceinline__ float roundtf(float x) {
    return __uint_as_float(f2tf32(x));
}

__device__ __forceinline__ void mma_tf32(float* d, const uint32_t* a,
                                         const uint32_t* b) {
    asm volatile(
        "mma.sync.aligned.m16n8k8.row.col.f32.tf32.tf32.f32 "
        "{%0,%1,%2,%3}, {%4,%5,%6,%7}, {%8,%9}, {%0,%1,%2,%3};"
        : "+f"(d[0]), "+f"(d[1]), "+f"(d[2]), "+f"(d[3])
        : "r"(a[0]), "r"(a[1]), "r"(a[2]), "r"(a[3]),
          "r"(b[0]), "r"(b[1]));
}

// ldmatrix x4: 4 tiles of 8 rows x 16B. Lanes 0-7 address tile0 rows, etc.
__device__ __forceinline__ void ldsm_x4(uint32_t* r, uint32_t addr) {
    asm volatile(
        "ldmatrix.sync.aligned.m8n8.x4.shared.b16 {%0,%1,%2,%3}, [%4];"
        : "=r"(r[0]), "=r"(r[1]), "=r"(r[2]), "=r"(r[3]) : "r"(addr));
}

__device__ __forceinline__ uint32_t smem_u32(const void* p) {
    uint32_t a;
    asm("{ .reg .u64 t; cvta.to.shared.u64 t, %1; cvt.u32.u64 %0, t; }"
        : "=r"(a) : "l"(p));
    return a;
}

#define CP_ASYNC16(dst, src) \
    asm volatile("cp.async.cg.shared.global [%0], [%1], 16;" \
                 :: "r"(dst), "l"(src))
#define CP_COMMIT() asm volatile("cp.async.commit_group;")
#define CP_WAIT(n)  asm volatile("cp.async.wait_group %0;" :: "n"(n))

// ---------------------------------------------------------------------------
__global__ __launch_bounds__(256) void round_tf32_kernel(
    const float* __restrict__ in, float* __restrict__ out, int n4)
{
    int i = blockIdx.x * blockDim.x + threadIdx.x;
    if (i < n4) {
        float4 v = ((const float4*)in)[i];
        v.x = roundtf(v.x); v.y = roundtf(v.y);
        v.z = roundtf(v.z); v.w = roundtf(v.w);
        ((float4*)out)[i] = v;
    }
}

__global__ __launch_bounds__(256) void transpose_kernel(
    const float* __restrict__ in, float* __restrict__ out, int R, int C)
{
    __shared__ float tile[32][33];
    int bx = blockIdx.x * 32, by = blockIdx.y * 32;
    int x = bx + threadIdx.x;
    #pragma unroll
    for (int i = 0; i < 32; i += 8) {
        int y = by + threadIdx.y + i;
        tile[threadIdx.y + i][threadIdx.x] = in[(size_t)y * C + x];
    }
    __syncthreads();
    int ox = by + threadIdx.x;
    #pragma unroll
    for (int i = 0; i < 32; i += 8) {
        int oy = bx + threadIdx.y + i;
        out[(size_t)oy * R + ox] = roundtf(tile[threadIdx.x][threadIdx.y + i]);
    }
}

// ---------------------------------------------------------------------------
// tf32 mma.sync GEMM with ldmatrix fragment loads.
// C[M,N] = A[M,K] @ Bt[N,K]^T + bias[N]. CTA 128x128, BK=32, 3-stage cp.async.
// ---------------------------------------------------------------------------
#define PADK 36

__global__ __launch_bounds__(256, 2) void gemm_tf32_kernel(
    const float* __restrict__ A, const float* __restrict__ Bt,
    const float* __restrict__ bias, float* __restrict__ C,
    int M, int N, int K, int round_out)
{
    extern __shared__ uint32_t smem[];
    const uint32_t sbase = smem_u32(smem);

    const int tid = threadIdx.x;
    const int wid = tid >> 5;
    const int lid = tid & 31;
    const int gid = lid >> 2;
    const int tig = lid & 3;
    const int lt  = lid >> 3;   // ldmatrix tile index 0..3
    const int lr  = lid & 7;    // ldmatrix row within tile

    const int bm = blockIdx.y * 128;
    const int bn = blockIdx.x * 128;

    const int mbase = (wid & 1) * 64;
    const int nbase = (wid >> 1) * 32;

    const int grow = tid >> 3;
    const int gc4  = tid & 7;

    // per-lane ldmatrix row offsets (word units)
    // A tiles: t0=(r,klo) t1=(r+8,klo) t2=(r,khi) t3=(r+8,khi)
    const uint32_t a_off = (uint32_t)((mbase + (lt & 1) * 8 + lr) * PADK
                                      + (lt >> 1) * 4);
    // B tiles: t0=(j,klo) t1=(j,khi) t2=(j+1,klo) t3=(j+1,khi)
    const uint32_t b_off = (uint32_t)((nbase + (lt >> 1) * 8 + lr) * PADK
                                      + (lt & 1) * 4);

    float acc[4][4][4];
    #pragma unroll
    for (int i = 0; i < 4; i++)
        #pragma unroll
        for (int j = 0; j < 4; j++)
            #pragma unroll
            for (int e = 0; e < 4; e++) acc[i][j][e] = 0.0f;

    const int NC = K >> 5;
    constexpr uint32_t STG = 128 * PADK * 4;

    auto issue = [&](int c) {
        const int p = c % 3;
        const float* Ab = A  + (size_t)bm * K + c * 32;
        const float* Bb = Bt + (size_t)bn * K + c * 32;
        const uint32_t aoff = sbase + (uint32_t)p * STG;
        const uint32_t boff = sbase + (uint32_t)(3 + p) * STG;
        #pragma unroll
        for (int i = 0; i < 4; i++) {
            int r = grow + 32 * i;
            uint32_t d = (uint32_t)(r * PADK + gc4 * 4) * 4u;
            CP_ASYNC16(aoff + d, Ab + (size_t)r * K + gc4 * 4);
            CP_ASYNC16(boff + d, Bb + (size_t)r * K + gc4 * 4);
        }
        CP_COMMIT();
    };

    issue(0);
    issue(1);

    for (int c = 0; c < NC; c++) {
        if (c + 2 < NC) { CP_WAIT(1); } else { CP_WAIT(0); }
        __syncthreads();
        if (c + 2 < NC) issue(c + 2);

        const uint32_t asb = sbase + (uint32_t)(c % 3) * STG + a_off * 4u;
        const uint32_t bsb = sbase + (uint32_t)(3 + c % 3) * STG + b_off * 4u;
        #pragma unroll
        for (int ks = 0; ks < 4; ks++) {
            const uint32_t k0b = (uint32_t)(ks * 8) * 4u;
            uint32_t af[4][4], bf[2][4];
            #pragma unroll
            for (int i = 0; i < 4; i++)
                ldsm_x4(af[i], asb + k0b + (uint32_t)(i * 16 * PADK) * 4u);
            #pragma unroll
            for (int p = 0; p < 2; p++)
                ldsm_x4(bf[p], bsb + k0b + (uint32_t)(p * 16 * PADK) * 4u);
            #pragma unroll
            for (int i = 0; i < 4; i++)
                #pragma unroll
                for (int j = 0; j < 4; j++)
                    mma_tf32(acc[i][j], af[i], bf[j >> 1] + (j & 1) * 2);
        }
    }

    #pragma unroll
    for (int j = 0; j < 4; j++) {
        const int col = bn + nbase + j * 8 + 2 * tig;
        const float bi0 = __ldg(bias + col);
        const float bi1 = __ldg(bias + col + 1);
        #pragma unroll
        for (int i = 0; i < 4; i++) {
            const int row0 = bm + mbase + i * 16 + gid;
            float2 v0 = { acc[i][j][0] + bi0, acc[i][j][1] + bi1 };
            float2 v1 = { acc[i][j][2] + bi0, acc[i][j][3] + bi1 };
            if (round_out) {
                v0.x = roundtf(v0.x); v0.y = roundtf(v0.y);
                v1.x = roundtf(v1.x); v1.y = roundtf(v1.y);
            }
            *(float2*)(C + (size_t)row0 * N + col) = v0;
            *(float2*)(C + (size_t)(row0 + 8) * N + col) = v1;
        }
    }
}

// ---------------------------------------------------------------------------
// Fused causal ALiBi attention, m16n8k8 tf32 mma.sync + ldmatrix frag loads.
// ---------------------------------------------------------------------------
#define STRD 68
#define VSTR 72

__global__ __launch_bounds__(256, 2) void attn_mma_kernel(
    const float* __restrict__ qkv, float* __restrict__ out)
{
    extern __shared__ uint32_t sm[];
    uint32_t* Qs = sm;                        // [128][STRD]
    uint32_t* Ks = Qs + 128 * STRD;           // [64][STRD]   [key][dh]
    uint32_t* Vs = Ks + 64 * STRD;            // [64][VSTR]   [key][dh]
    uint32_t* Ps = Vs + 64 * VSTR;            // [128][STRD]

    const int tid = threadIdx.x;
    const int wid = tid >> 5;
    const int lid = tid & 31;
    const int gid = lid >> 2;
    const int tig = lid & 3;
    const int lt  = lid >> 3;
    const int lr  = lid & 7;

    const int qt = (int)gridDim.x - 1 - (int)blockIdx.x;
    const int bh = blockIdx.y;
    const int b  = bh >> 4;
    const int h  = bh & 15;

    const float slope = exp2f(-0.5f * (float)(h + 1));
    const float scale = 0.125f;

    const float* base = qkv + (size_t)b * LL * 3072 + h * 64;
    const uint32_t qsb = smem_u32(Qs);
    const uint32_t ksb = smem_u32(Ks);
    const uint32_t vsb = smem_u32(Vs);
    const uint32_t psb = smem_u32(Ps);

    const int mbase = wid * 16;
    const int row0g = qt * 128 + mbase + gid;

    // ldmatrix per-lane offsets (bytes)
    const uint32_t a_off = (uint32_t)((mbase + (lt & 1) * 8 + lr) * STRD
                                      + (lt >> 1) * 4) * 4u;   // Q / P A-frags
    const uint32_t k_off = (uint32_t)(((lt >> 1) * 8 + lr) * STRD
                                      + (lt & 1) * 4) * 4u;    // K B-frags

    // Q tile via cp.async
    #pragma unroll
    for (int i = 0; i < 8; i++) {
        int idx = tid + i * 256;
        int r = idx >> 4;
        int c4 = idx & 15;
        CP_ASYNC16(qsb + (uint32_t)(r * STRD + c4 * 4) * 4u,
                   base + (size_t)(qt * 128 + r) * 3072 + c4 * 4);
    }
    CP_COMMIT();

    float m0 = -1e30f, m1 = -1e30f, l0 = 0.0f, l1 = 0.0f;
    float O[8][4];
    #pragma unroll
    for (int j = 0; j < 8; j++)
        #pragma unroll
        for (int e = 0; e < 4; e++) O[j][e] = 0.0f;

    const float sq0 = slope * (float)row0g;
    const float sq1 = slope * (float)(row0g + 8);

    auto do_chunk = [&](int kt, bool MASKED) {
        __syncthreads();

        #pragma unroll
        for (int i = 0; i < 4; i++) {
            int idx = tid + i * 256;
            int r = idx >> 4;
            int c4 = idx & 15;
            const float* rp = base + (size_t)(kt * 64 + r) * 3072;
            CP_ASYNC16(ksb + (uint32_t)(r * STRD + c4 * 4) * 4u, rp + 1024 + c4 * 4);
            CP_ASYNC16(vsb + (uint32_t)(r * VSTR + c4 * 4) * 4u, rp + 2048 + c4 * 4);
        }
        CP_COMMIT();
        CP_WAIT(0);
        __syncthreads();

        // S = Q @ K^T
        float s[8][4];
        #pragma unroll
        for (int j = 0; j < 8; j++)
            #pragma unroll
            for (int e = 0; e < 4; e++) s[j][e] = 0.0f;

        #pragma unroll
        for (int ks = 0; ks < 8; ks++) {
            const uint32_t k0b = (uint32_t)(ks * 8) * 4u;
            uint32_t a[4], bf[4][4];
            ldsm_x4(a, qsb + a_off + k0b);
            #pragma unroll
            for (int p = 0; p < 4; p++)
                ldsm_x4(bf[p], ksb + k_off + k0b + (uint32_t)(p * 16 * STRD) * 4u);
            #pragma unroll
            for (int j = 0; j < 8; j++)
                mma_tf32(s[j], a, bf[j >> 1] + (j & 1) * 2);
        }

        const int kc0 = kt * 64 + 2 * tig;
        float mv0 = -1e30f, mv1 = -1e30f;
        #pragma unroll
        for (int j = 0; j < 8; j++) {
            const float sk0 = slope * (float)(kc0 + j * 8);
            const float sk1 = sk0 + slope;
            float v0 = s[j][0] * scale + sk0 - sq0;
            float v1 = s[j][1] * scale + sk1 - sq0;
            float v2 = s[j][2] * scale + sk0 - sq1;
            float v3 = s[j][3] * scale + sk1 - sq1;
            if (MASKED) {
                int kg0 = kc0 + j * 8, kg1 = kg0 + 1;
                v0 = (kg0 <= row0g)     ? v0 : -1e30f;
                v1 = (kg1 <= row0g)     ? v1 : -1e30f;
                v2 = (kg0 <= row0g + 8) ? v2 : -1e30f;
                v3 = (kg1 <= row0g + 8) ? v3 : -1e30f;
            }
            s[j][0] = v0; s[j][1] = v1; s[j][2] = v2; s[j][3] = v3;
            mv0 = fmaxf(mv0, fmaxf(v0, v1));
            mv1 = fmaxf(mv1, fmaxf(v2, v3));
        }
        mv0 = fmaxf(mv0, __shfl_xor_sync(0xffffffffu, mv0, 1));
        mv0 = fmaxf(mv0, __shfl_xor_sync(0xffffffffu, mv0, 2));
        mv1 = fmaxf(mv1, __shfl_xor_sync(0xffffffffu, mv1, 1));
        mv1 = fmaxf(mv1, __shfl_xor_sync(0xffffffffu, mv1, 2));

        const float mn0 = fmaxf(m0, mv0);
        const float mn1 = fmaxf(m1, mv1);

        float rs0 = 0.0f, rs1 = 0.0f;
        #pragma unroll
        for (int j = 0; j < 8; j++) {
            s[j][0] = __expf(s[j][0] - mn0);
            s[j][1] = __expf(s[j][1] - mn0);
            s[j][2] = __expf(s[j][2] - mn1);
            s[j][3] = __expf(s[j][3] - mn1);
            rs0 += s[j][0] + s[j][1];
            rs1 += s[j][2] + s[j][3];
        }
        rs0 += __shfl_xor_sync(0xffffffffu, rs0, 1);
        rs0 += __shfl_xor_sync(0xffffffffu, rs0, 2);
        rs1 += __shfl_xor_sync(0xffffffffu, rs1, 1);
        rs1 += __shfl_xor_sync(0xffffffffu, rs1, 2);

        const float c0 = __expf(m0 - mn0);
        const float c1 = __expf(m1 - mn1);
        l0 = l0 * c0 + rs0;
        l1 = l1 * c1 + rs1;
        m0 = mn0; m1 = mn1;
        #pragma unroll
        for (int j = 0; j < 8; j++) {
            O[j][0] *= c0; O[j][1] *= c0;
            O[j][2] *= c1; O[j][3] *= c1;
        }

        // P -> smem (warp-private rows)
        #pragma unroll
        for (int j = 0; j < 8; j++) {
            uint32_t* pp = Ps + (mbase + gid) * STRD + j * 8 + 2 * tig;
            uint2 w0 = { f2tf32(s[j][0]), f2tf32(s[j][1]) };
            uint2 w1 = { f2tf32(s[j][2]), f2tf32(s[j][3]) };
            *(uint2*)pp = w0;
            *(uint2*)(pp + 8 * STRD) = w1;
        }
        __syncwarp();

        // O += P @ V
        #pragma unroll
        for (int ks = 0; ks < 8; ks++) {
            const uint32_t k0b = (uint32_t)(ks * 8) * 4u;
            uint32_t a[4];
            ldsm_x4(a, psb + a_off + k0b);
            #pragma unroll
            for (int j = 0; j < 8; j++) {
                uint32_t bf[2];
                const uint32_t* vp = Vs + (ks * 8 + tig) * VSTR + j * 8 + gid;
                bf[0] = vp[0]; bf[1] = vp[4 * VSTR];
                mma_tf32(O[j], a, bf);
            }
        }
    };

    const int nfull = 2 * qt;
    for (int kt = 0; kt < nfull; kt++) do_chunk(kt, false);
    do_chunk(nfull, true);
    do_chunk(nfull + 1, true);

    const float inv0 = 1.0f / l0;
    const float inv1 = 1.0f / l1;
    #pragma unroll
    for (int j = 0; j < 8; j++) {
        const int col = h * 64 + j * 8 + 2 * tig;
        float2 v0 = { roundtf(O[j][0] * inv0), roundtf(O[j][1] * inv0) };
        float2 v1 = { roundtf(O[j][2] * inv1), roundtf(O[j][3] * inv1) };
        *(float2*)(out + ((size_t)b * LL + row0g) * DD + col) = v0;
        *(float2*)(out + ((size_t)b * LL + row0g + 8) * DD + col) = v1;
    }
}

// ---------------------------------------------------------------------------
extern "C" void kernel_launch(void* const* d_in, const int* in_sizes, int n_in,
                              void* d_out, int out_size)
{
    const float* x     = (const float*)d_in[0];
    const float* w_in  = (const float*)d_in[1];
    const float* b_in  = (const float*)d_in[2];
    const float* w_out = (const float*)d_in[3];
    const float* b_out = (const float*)d_in[4];
    float* out = (float*)d_out;

    float *xt, *qkv, *att, *wtin, *wtout;
    cudaGetSymbolAddress((void**)&xt, g_xt);
    cudaGetSymbolAddress((void**)&qkv, g_qkv);
    cudaGetSymbolAddress((void**)&att, g_att);
    cudaGetSymbolAddress((void**)&wtin, g_wtin);
    cudaGetSymbolAddress((void**)&wtout, g_wtout);

    const int M = BB * LL;
    const int GEMM_SMEM = 6 * 128 * PADK * 4;                        // 110592
    const int ATTN_SMEM = (128 * STRD + 64 * STRD + 64 * VSTR + 128 * STRD) * 4;
    static bool attr_set = false;
    if (!attr_set) {
        cudaFuncSetAttribute(gemm_tf32_kernel,
                             cudaFuncAttributeMaxDynamicSharedMemorySize, GEMM_SMEM);
        cudaFuncSetAttribute(attn_mma_kernel,
                             cudaFuncAttributeMaxDynamicSharedMemorySize, ATTN_SMEM);
        attr_set = true;
    }

    // 0) Round x; transpose+round weights
    {
        int n4 = M * DD / 4;
        round_tf32_kernel<<<(n4 + 255) / 256, 256>>>(x, xt, n4);
        dim3 blk(32, 8);
        transpose_kernel<<<dim3(3 * DD / 32, DD / 32), blk>>>(w_in, wtin, DD, 3 * DD);
        transpose_kernel<<<dim3(DD / 32, DD / 32), blk>>>(w_out, wtout, DD, DD);
    }

    // 1) QKV projection
    {
        dim3 grid(3 * DD / 128, M / 128);
        gemm_tf32_kernel<<<grid, 256, GEMM_SMEM>>>(xt, wtin, b_in, qkv,
                                                   M, 3 * DD, DD, 1);
    }

    // 2) Fused causal ALiBi attention
    {
        dim3 grid(LL / 128, BB * HH);
        attn_mma_kernel<<<grid, 256, ATTN_SMEM>>>(qkv, att);
    }

    // 3) Output projection
    {
        dim3 grid(DD / 128, M / 128);
        gemm_tf32_kernel<<<grid, 256, GEMM_SMEM>>>(att, wtout, b_out, out,
                                                   M, DD, DD, 0);
    }
}

// round 8
// speedup vs baseline: 3.4886x; 1.0363x over previous
#include <cuda_runtime.h>
#include <cstdint>

#define BB   2
#define LL   2048
#define DD   1024
#define HH   16
#define DHH  64

// Scratch (allocation-free: device globals) — all values stored tf32-rounded
__device__ float g_xt[(size_t)BB * LL * DD];
__device__ float g_qkv[(size_t)BB * LL * 3 * DD];
__device__ float g_att[(size_t)BB * LL * DD];
__device__ float g_wtin[(size_t)3 * DD * DD];
__device__ float g_wtout[(size_t)DD * DD];

// ---------------------------------------------------------------------------
// helpers
// ---------------------------------------------------------------------------
__device__ __forceinline__ uint32_t f2tf32(float x) {
    uint32_t r;
    asm("cvt.rna.tf32.f32 %0, %1;" : "=r"(r) : "f"(x));
    return r;
}
__device__ __forceinline__ float roundtf(float x) {
    return __uint_as_float(f2tf32(x));
}
__device__ __forceinline__ float ex2f(float x) {
    float y;
    asm("ex2.approx.f32 %0, %1;" : "=f"(y) : "f"(x));
    return y;
}

__device__ __forceinline__ void mma_tf32(float* d, const uint32_t* a,
                                         const uint32_t* b) {
    asm volatile(
        "mma.sync.aligned.m16n8k8.row.col.f32.tf32.tf32.f32 "
        "{%0,%1,%2,%3}, {%4,%5,%6,%7}, {%8,%9}, {%0,%1,%2,%3};"
        : "+f"(d[0]), "+f"(d[1]), "+f"(d[2]), "+f"(d[3])
        : "r"(a[0]), "r"(a[1]), "r"(a[2]), "r"(a[3]),
          "r"(b[0]), "r"(b[1]));
}

__device__ __forceinline__ void ldsm_x4(uint32_t* r, uint32_t addr) {
    asm volatile(
        "ldmatrix.sync.aligned.m8n8.x4.shared.b16 {%0,%1,%2,%3}, [%4];"
        : "=r"(r[0]), "=r"(r[1]), "=r"(r[2]), "=r"(r[3]) : "r"(addr));
}

__device__ __forceinline__ uint32_t smem_u32(const void* p) {
    uint32_t a;
    asm("{ .reg .u64 t; cvta.to.shared.u64 t, %1; cvt.u32.u64 %0, t; }"
        : "=r"(a) : "l"(p));
    return a;
}

#define CP_ASYNC16(dst, src) \
    asm volatile("cp.async.cg.shared.global [%0], [%1], 16;" \
                 :: "r"(dst), "l"(src))
#define CP_COMMIT() asm volatile("cp.async.commit_group;")
#define CP_WAIT(n)  asm volatile("cp.async.wait_group %0;" :: "n"(n))

// ---------------------------------------------------------------------------
__global__ __launch_bounds__(256) void round_tf32_kernel(
    const float* __restrict__ in, float* __restrict__ out, int n4)
{
    int i = blockIdx.x * blockDim.x + threadIdx.x;
    if (i < n4) {
        float4 v = ((const float4*)in)[i];
        v.x = roundtf(v.x); v.y = roundtf(v.y);
        v.z = roundtf(v.z); v.w = roundtf(v.w);
        ((float4*)out)[i] = v;
    }
}

__global__ __launch_bounds__(256) void transpose_kernel(
    const float* __restrict__ in, float* __restrict__ out, int R, int C)
{
    __shared__ float tile[32][33];
    int bx = blockIdx.x * 32, by = blockIdx.y * 32;
    int x = bx + threadIdx.x;
    #pragma unroll
    for (int i = 0; i < 32; i += 8) {
        int y = by + threadIdx.y + i;
        tile[threadIdx.y + i][threadIdx.x] = in[(size_t)y * C + x];
    }
    __syncthreads();
    int ox = by + threadIdx.x;
    #pragma unroll
    for (int i = 0; i < 32; i += 8) {
        int oy = bx + threadIdx.y + i;
        out[(size_t)oy * R + ox] = roundtf(tile[threadIdx.x][threadIdx.y + i]);
    }
}

// ---------------------------------------------------------------------------
// tf32 mma.sync GEMM: C[M,N] = A[M,K] @ Bt[N,K]^T + bias[N]
// CTA tile 128x256, warp tile 64x64 (8 warps, 2Mx4N), BK=32,
// 3-stage cp.async, ldmatrix fragment loads.
// ---------------------------------------------------------------------------
#define PADK 36

__global__ __launch_bounds__(256) void gemm_tf32_kernel(
    const float* __restrict__ A, const float* __restrict__ Bt,
    const float* __restrict__ bias, float* __restrict__ C,
    int M, int N, int K, int round_out)
{
    extern __shared__ uint32_t smem[];
    const uint32_t sbase = smem_u32(smem);

    const int tid = threadIdx.x;
    const int wid = tid >> 5;
    const int lid = tid & 31;
    const int gid = lid >> 2;
    const int tig = lid & 3;
    const int lt  = lid >> 3;
    const int lr  = lid & 7;

    const int bm = blockIdx.y * 128;
    const int bn = blockIdx.x * 256;

    const int mbase = (wid & 1) * 64;
    const int nbase = (wid >> 1) * 64;

    const int grow = tid >> 3;   // 0..31
    const int gc4  = tid & 7;

    const uint32_t a_off = (uint32_t)((mbase + (lt & 1) * 8 + lr) * PADK
                                      + (lt >> 1) * 4);
    const uint32_t b_off = (uint32_t)((nbase + (lt >> 1) * 8 + lr) * PADK
                                      + (lt & 1) * 4);

    float acc[4][8][4];
    #pragma unroll
    for (int i = 0; i < 4; i++)
        #pragma unroll
        for (int j = 0; j < 8; j++)
            #pragma unroll
            for (int e = 0; e < 4; e++) acc[i][j][e] = 0.0f;

    const int NC = K >> 5;
    constexpr uint32_t ASTG = 128 * PADK * 4;   // bytes per A stage
    constexpr uint32_t BSTG = 256 * PADK * 4;   // bytes per B stage
    constexpr uint32_t BBASE = 3 * ASTG;

    auto issue = [&](int c) {
        const int p = c % 3;
        const float* Ab = A  + (size_t)bm * K + c * 32;
        const float* Bb = Bt + (size_t)bn * K + c * 32;
        const uint32_t aoff = sbase + (uint32_t)p * ASTG;
        const uint32_t boff = sbase + BBASE + (uint32_t)p * BSTG;
        #pragma unroll
        for (int i = 0; i < 4; i++) {
            int r = grow + 32 * i;
            uint32_t d = (uint32_t)(r * PADK + gc4 * 4) * 4u;
            CP_ASYNC16(aoff + d, Ab + (size_t)r * K + gc4 * 4);
        }
        #pragma unroll
        for (int i = 0; i < 8; i++) {
            int r = grow + 32 * i;
            uint32_t d = (uint32_t)(r * PADK + gc4 * 4) * 4u;
            CP_ASYNC16(boff + d, Bb + (size_t)r * K + gc4 * 4);
        }
        CP_COMMIT();
    };

    issue(0);
    issue(1);

    for (int c = 0; c < NC; c++) {
        if (c + 2 < NC) { CP_WAIT(1); } else { CP_WAIT(0); }
        __syncthreads();
        if (c + 2 < NC) issue(c + 2);

        const uint32_t asb = sbase + (uint32_t)(c % 3) * ASTG + a_off * 4u;
        const uint32_t bsb = sbase + BBASE + (uint32_t)(c % 3) * BSTG + b_off * 4u;
        #pragma unroll
        for (int ks = 0; ks < 4; ks++) {
            const uint32_t k0b = (uint32_t)(ks * 8) * 4u;
            uint32_t af[4][4], bf[4][4];
            #pragma unroll
            for (int i = 0; i < 4; i++)
                ldsm_x4(af[i], asb + k0b + (uint32_t)(i * 16 * PADK) * 4u);
            #pragma unroll
            for (int p = 0; p < 4; p++)
                ldsm_x4(bf[p], bsb + k0b + (uint32_t)(p * 16 * PADK) * 4u);
            #pragma unroll
            for (int i = 0; i < 4; i++)
                #pragma unroll
                for (int j = 0; j < 8; j++)
                    mma_tf32(acc[i][j], af[i], bf[j >> 1] + (j & 1) * 2);
        }
    }

    #pragma unroll
    for (int j = 0; j < 8; j++) {
        const int col = bn + nbase + j * 8 + 2 * tig;
        const float bi0 = __ldg(bias + col);
        const float bi1 = __ldg(bias + col + 1);
        #pragma unroll
        for (int i = 0; i < 4; i++) {
            const int row0 = bm + mbase + i * 16 + gid;
            float2 v0 = { acc[i][j][0] + bi0, acc[i][j][1] + bi1 };
            float2 v1 = { acc[i][j][2] + bi0, acc[i][j][3] + bi1 };
            if (round_out) {
                v0.x = roundtf(v0.x); v0.y = roundtf(v0.y);
                v1.x = roundtf(v1.x); v1.y = roundtf(v1.y);
            }
            *(float2*)(C + (size_t)row0 * N + col) = v0;
            *(float2*)(C + (size_t)(row0 + 8) * N + col) = v1;
        }
    }
}

// ---------------------------------------------------------------------------
// Fused causal ALiBi attention, m16n8k8 tf32 mma.sync + ldmatrix.
// Double-buffered K/V via cp.async (prefetch kt+1 during compute of kt).
// Q fragments hoisted to registers; Q smem region reused for P.
// Softmax in exp2 domain (log2e folded into scale/slope).
// ---------------------------------------------------------------------------
#define STRD 68
#define VSTR 72

__global__ __launch_bounds__(256) void attn_mma_kernel(
    const float* __restrict__ qkv, float* __restrict__ out)
{
    extern __shared__ uint32_t sm[];
    // layout (words): QP [128*STRD] (Q load, then P), K[2][64*STRD], V[2][64*VSTR]
    uint32_t* QP = sm;
    const uint32_t qpb = smem_u32(QP);
    const uint32_t kb0 = qpb + 128 * STRD * 4;
    const uint32_t kb1 = kb0 + 64 * STRD * 4;
    const uint32_t vb0 = kb1 + 64 * STRD * 4;
    const uint32_t vb1 = vb0 + 64 * VSTR * 4;

    const int tid = threadIdx.x;
    const int wid = tid >> 5;
    const int lid = tid & 31;
    const int gid = lid >> 2;
    const int tig = lid & 3;
    const int lt  = lid >> 3;
    const int lr  = lid & 7;

    const int qt = (int)gridDim.x - 1 - (int)blockIdx.x;  // heavy tiles first
    const int bh = blockIdx.y;
    const int b  = bh >> 4;
    const int h  = bh & 15;

    constexpr float L2E = 1.4426950408889634f;
    const float slope2 = exp2f(-0.5f * (float)(h + 1)) * L2E;
    const float scale2 = 0.125f * L2E;

    const float* base = qkv + (size_t)b * LL * 3072 + h * 64;

    const int mbase = wid * 16;
    const int row0g = qt * 128 + mbase + gid;

    const uint32_t a_off = (uint32_t)((mbase + (lt & 1) * 8 + lr) * STRD
                                      + (lt >> 1) * 4) * 4u;
    const uint32_t k_off = (uint32_t)(((lt >> 1) * 8 + lr) * STRD
                                      + (lt & 1) * 4) * 4u;

    auto issue_kv = [&](int kt, uint32_t kb, uint32_t vb) {
        #pragma unroll
        for (int i = 0; i < 4; i++) {
            int idx = tid + i * 256;
            int r = idx >> 4;
            int c4 = idx & 15;
            const float* rp = base + (size_t)(kt * 64 + r) * 3072;
            CP_ASYNC16(kb + (uint32_t)(r * STRD + c4 * 4) * 4u, rp + 1024 + c4 * 4);
            CP_ASYNC16(vb + (uint32_t)(r * VSTR + c4 * 4) * 4u, rp + 2048 + c4 * 4);
        }
        CP_COMMIT();
    };

    // prologue: Q tile + KV chunk 0
    #pragma unroll
    for (int i = 0; i < 8; i++) {
        int idx = tid + i * 256;
        int r = idx >> 4;
        int c4 = idx & 15;
        CP_ASYNC16(qpb + (uint32_t)(r * STRD + c4 * 4) * 4u,
                   base + (size_t)(qt * 128 + r) * 3072 + c4 * 4);
    }
    CP_COMMIT();
    issue_kv(0, kb0, vb0);
    CP_WAIT(0);
    __syncthreads();

    // hoist Q fragments into registers (constant across all chunks)
    uint32_t qf[8][4];
    #pragma unroll
    for (int ks = 0; ks < 8; ks++)
        ldsm_x4(qf[ks], qpb + a_off + (uint32_t)(ks * 8) * 4u);

    float m0 = -1e30f, m1 = -1e30f, l0 = 0.0f, l1 = 0.0f;
    float O[8][4];
    #pragma unroll
    for (int j = 0; j < 8; j++)
        #pragma unroll
        for (int e = 0; e < 4; e++) O[j][e] = 0.0f;

    const float sq0 = slope2 * (float)row0g;
    const float sq1 = slope2 * (float)(row0g + 8);

    const int nfull = 2 * qt;
    const int nkt = nfull + 2;

    auto compute = [&](int kt, bool MASKED) {
        const uint32_t kb = (kt & 1) ? kb1 : kb0;
        const uint32_t vb = (kt & 1) ? vb1 : vb0;
        const uint32_t* Vsp = (const uint32_t*)((kt & 1)
            ? (sm + (kb1 - qpb) / 4 + 64 * STRD + 0)  // placeholder, fixed below
            : nullptr);
        (void)Vsp;

        // S = Q @ K^T
        float s[8][4];
        #pragma unroll
        for (int j = 0; j < 8; j++)
            #pragma unroll
            for (int e = 0; e < 4; e++) s[j][e] = 0.0f;

        #pragma unroll
        for (int ks = 0; ks < 8; ks++) {
            const uint32_t k0b = (uint32_t)(ks * 8) * 4u;
            uint32_t bf[4][4];
            #pragma unroll
            for (int p = 0; p < 4; p++)
                ldsm_x4(bf[p], kb + k_off + k0b + (uint32_t)(p * 16 * STRD) * 4u);
            #pragma unroll
            for (int j = 0; j < 8; j++)
                mma_tf32(s[j], qf[ks], bf[j >> 1] + (j & 1) * 2);
        }

        const int kc0 = kt * 64 + 2 * tig;
        float mv0 = -1e30f, mv1 = -1e30f;
        #pragma unroll
        for (int j = 0; j < 8; j++) {
            const float sk0 = slope2 * (float)(kc0 + j * 8);
            const float sk1 = sk0 + slope2;
            float v0 = s[j][0] * scale2 + sk0 - sq0;
            float v1 = s[j][1] * scale2 + sk1 - sq0;
            float v2 = s[j][2] * scale2 + sk0 - sq1;
            float v3 = s[j][3] * scale2 + sk1 - sq1;
            if (MASKED) {
                int kg0 = kc0 + j * 8, kg1 = kg0 + 1;
                v0 = (kg0 <= row0g)     ? v0 : -1e30f;
                v1 = (kg1 <= row0g)     ? v1 : -1e30f;
                v2 = (kg0 <= row0g + 8) ? v2 : -1e30f;
                v3 = (kg1 <= row0g + 8) ? v3 : -1e30f;
            }
            s[j][0] = v0; s[j][1] = v1; s[j][2] = v2; s[j][3] = v3;
            mv0 = fmaxf(mv0, fmaxf(v0, v1));
            mv1 = fmaxf(mv1, fmaxf(v2, v3));
        }
        mv0 = fmaxf(mv0, __shfl_xor_sync(0xffffffffu, mv0, 1));
        mv0 = fmaxf(mv0, __shfl_xor_sync(0xffffffffu, mv0, 2));
        mv1 = fmaxf(mv1, __shfl_xor_sync(0xffffffffu, mv1, 1));
        mv1 = fmaxf(mv1, __shfl_xor_sync(0xffffffffu, mv1, 2));

        const float mn0 = fmaxf(m0, mv0);
        const float mn1 = fmaxf(m1, mv1);

        float rs0 = 0.0f, rs1 = 0.0f;
        #pragma unroll
        for (int j = 0; j < 8; j++) {
            s[j][0] = ex2f(s[j][0] - mn0);
            s[j][1] = ex2f(s[j][1] - mn0);
            s[j][2] = ex2f(s[j][2] - mn1);
            s[j][3] = ex2f(s[j][3] - mn1);
            rs0 += s[j][0] + s[j][1];
            rs1 += s[j][2] + s[j][3];
        }
        rs0 += __shfl_xor_sync(0xffffffffu, rs0, 1);
        rs0 += __shfl_xor_sync(0xffffffffu, rs0, 2);
        rs1 += __shfl_xor_sync(0xffffffffu, rs1, 1);
        rs1 += __shfl_xor_sync(0xffffffffu, rs1, 2);

        const float c0 = ex2f(m0 - mn0);
        const float c1 = ex2f(m1 - mn1);
        l0 = l0 * c0 + rs0;
        l1 = l1 * c1 + rs1;
        m0 = mn0; m1 = mn1;
        #pragma unroll
        for (int j = 0; j < 8; j++) {
            O[j][0] *= c0; O[j][1] *= c0;
            O[j][2] *= c1; O[j][3] *= c1;
        }

        // P -> smem (warp-private rows in the QP region)
        #pragma unroll
        for (int j = 0; j < 8; j++) {
            uint32_t* pp = QP + (mbase + gid) * STRD + j * 8 + 2 * tig;
            uint2 w0 = { f2tf32(s[j][0]), f2tf32(s[j][1]) };
            uint2 w1 = { f2tf32(s[j][2]), f2tf32(s[j][3]) };
            *(uint2*)pp = w0;
            *(uint2*)(pp + 8 * STRD) = w1;
        }
        __syncwarp();

        // O += P @ V
        const uint32_t* Vbase = sm + (vb - qpb) / 4;
        #pragma unroll
        for (int ks = 0; ks < 8; ks++) {
            uint32_t a[4];
            ldsm_x4(a, qpb + a_off + (uint32_t)(ks * 8) * 4u);
            #pragma unroll
            for (int j = 0; j < 8; j++) {
                uint32_t bf[2];
                const uint32_t* vp = Vbase + (ks * 8 + tig) * VSTR + j * 8 + gid;
                bf[0] = vp[0]; bf[1] = vp[4 * VSTR];
                mma_tf32(O[j], a, bf);
            }
        }
    };

    int kt = 0;
    for (; kt < nfull; kt++) {
        issue_kv(kt + 1, (kt & 1) ? kb0 : kb1, (kt & 1) ? vb0 : vb1);
        compute(kt, false);
        CP_WAIT(0);
        __syncthreads();
    }
    // masked diagonal chunks
    {
        issue_kv(kt + 1, (kt & 1) ? kb0 : kb1, (kt & 1) ? vb0 : vb1);
        compute(kt, true);
        CP_WAIT(0);
        __syncthreads();
        kt++;
        compute(kt, true);
    }

    const float inv0 = 1.0f / l0;
    const float inv1 = 1.0f / l1;
    #pragma unroll
    for (int j = 0; j < 8; j++) {
        const int col = h * 64 + j * 8 + 2 * tig;
        float2 v0 = { roundtf(O[j][0] * inv0), roundtf(O[j][1] * inv0) };
        float2 v1 = { roundtf(O[j][2] * inv1), roundtf(O[j][3] * inv1) };
        *(float2*)(out + ((size_t)b * LL + row0g) * DD + col) = v0;
        *(float2*)(out + ((size_t)b * LL + row0g + 8) * DD + col) = v1;
    }
}

// ---------------------------------------------------------------------------
extern "C" void kernel_launch(void* const* d_in, const int* in_sizes, int n_in,
                              void* d_out, int out_size)
{
    const float* x     = (const float*)d_in[0];
    const float* w_in  = (const float*)d_in[1];
    const float* b_in  = (const float*)d_in[2];
    const float* w_out = (const float*)d_in[3];
    const float* b_out = (const float*)d_in[4];
    float* out = (float*)d_out;

    float *xt, *qkv, *att, *wtin, *wtout;
    cudaGetSymbolAddress((void**)&xt, g_xt);
    cudaGetSymbolAddress((void**)&qkv, g_qkv);
    cudaGetSymbolAddress((void**)&att, g_att);
    cudaGetSymbolAddress((void**)&wtin, g_wtin);
    cudaGetSymbolAddress((void**)&wtout, g_wtout);

    const int M = BB * LL;
    const int GEMM_SMEM = 3 * (128 + 256) * PADK * 4;                // 165888
    const int ATTN_SMEM = (128 * STRD + 2 * 64 * STRD + 2 * 64 * VSTR) * 4; // 106496
    static bool attr_set = false;
    if (!attr_set) {
        cudaFuncSetAttribute(gemm_tf32_kernel,
                             cudaFuncAttributeMaxDynamicSharedMemorySize, GEMM_SMEM);
        cudaFuncSetAttribute(attn_mma_kernel,
                             cudaFuncAttributeMaxDynamicSharedMemorySize, ATTN_SMEM);
        attr_set = true;
    }

    // 0) Round x; transpose+round weights
    {
        int n4 = M * DD / 4;
        round_tf32_kernel<<<(n4 + 255) / 256, 256>>>(x, xt, n4);
        dim3 blk(32, 8);
        transpose_kernel<<<dim3(3 * DD / 32, DD / 32), blk>>>(w_in, wtin, DD, 3 * DD);
        transpose_kernel<<<dim3(DD / 32, DD / 32), blk>>>(w_out, wtout, DD, DD);
    }

    // 1) QKV projection
    {
        dim3 grid(3 * DD / 256, M / 128);
        gemm_tf32_kernel<<<grid, 256, GEMM_SMEM>>>(xt, wtin, b_in, qkv,
                                                   M, 3 * DD, DD, 1);
    }

    // 2) Fused causal ALiBi attention
    {
        dim3 grid(LL / 128, BB * HH);
        attn_mma_kernel<<<grid, 256, ATTN_SMEM>>>(qkv, att);
    }

    // 3) Output projection
    {
        dim3 grid(DD / 256, M / 128);
        gemm_tf32_kernel<<<grid, 256, GEMM_SMEM>>>(att, wtout, b_out, out,
                                                   M, DD, DD, 0);
    }
}